// round 1
// baseline (speedup 1.0000x reference)
#include <cuda_runtime.h>
#include <math.h>

#define NN   20000
#define EE   160000
#define HIDD 128
#define HEADS 4
#define QKVD (HEADS*HIDD)   // 512
#define INDIM 256

// ---------------- scratch (device globals; no allocation allowed) ----------
__device__ float g_h [NN*HIDD];     // hidden in
__device__ float g_h2[NN*HIDD];     // hidden out of layer1
__device__ float g_q [NN*QKVD];
__device__ float g_k [NN*QKVD];
__device__ float g_v [NN*QKVD];
__device__ float g_s [NN*HIDD];     // skip projection
__device__ int   g_deg[NN];
__device__ int   g_cursor[NN];
__device__ int   g_rowptr[NN+1];
__device__ int   g_col[EE];         // src node per CSR slot (sorted by dst)

// ---------------- CSR build ------------------------------------------------
__global__ void init_kernel() {
    int i = blockIdx.x * blockDim.x + threadIdx.x;
    if (i < NN) { g_deg[i] = 0; g_cursor[i] = 0; }
}

__global__ void count_kernel(const int* __restrict__ ei) {
    int e = blockIdx.x * blockDim.x + threadIdx.x;
    if (e < EE) atomicAdd(&g_deg[ei[EE + e]], 1);   // dst = ei[1][e]
}

// single-block exclusive scan of g_deg -> g_rowptr
__global__ void scan_kernel() {
    const int T = 1024;
    const int CH = (NN + T - 1) / T;  // 20
    int t = threadIdx.x;
    int lane = t & 31, wid = t >> 5;
    int vals[CH];
    int base = t * CH;
    int s = 0;
    #pragma unroll
    for (int i = 0; i < CH; i++) {
        int idx = base + i;
        int d = (idx < NN) ? g_deg[idx] : 0;
        vals[i] = d; s += d;
    }
    // warp inclusive scan
    int x = s;
    #pragma unroll
    for (int o = 1; o < 32; o <<= 1) {
        int y = __shfl_up_sync(0xffffffffu, x, o);
        if (lane >= o) x += y;
    }
    __shared__ int wsum[32];
    if (lane == 31) wsum[wid] = x;
    __syncthreads();
    if (wid == 0) {
        int w = wsum[lane];
        #pragma unroll
        for (int o = 1; o < 32; o <<= 1) {
            int y = __shfl_up_sync(0xffffffffu, w, o);
            if (lane >= o) w += y;
        }
        wsum[lane] = w;
    }
    __syncthreads();
    int excl = x - s + ((wid > 0) ? wsum[wid - 1] : 0);
    int off = excl;
    #pragma unroll
    for (int i = 0; i < CH; i++) {
        int idx = base + i;
        if (idx < NN) g_rowptr[idx] = off;
        off += vals[i];
    }
    if (t == T - 1) g_rowptr[NN] = off;  // == EE
}

__global__ void scatter_kernel(const int* __restrict__ ei) {
    int e = blockIdx.x * blockDim.x + threadIdx.x;
    if (e < EE) {
        int d = ei[EE + e];
        int pos = atomicAdd(&g_cursor[d], 1);
        g_col[g_rowptr[d] + pos] = ei[e];   // src = ei[0][e]
    }
}

// ---------------- fp32 tiled GEMM: C = A[M,K] @ B[K,Nc] + bias (opt relu) --
template<int BM, int BN, int BK, int TM, int TN>
__global__ void gemm_kernel(const float* __restrict__ A,
                            const float* __restrict__ B,
                            const float* __restrict__ bias,
                            float* __restrict__ C,
                            int M, int Nc, int K, int relu)
{
    __shared__ float As[BK][BM];
    __shared__ float Bs[BK][BN];
    int tid = threadIdx.x;                // 256 threads
    int tx = tid % (BN / TN);             // 16
    int ty = tid / (BN / TN);             // 16
    int row0 = blockIdx.y * BM;
    int col0 = blockIdx.x * BN;

    float acc[TM][TN];
    #pragma unroll
    for (int i = 0; i < TM; i++)
        #pragma unroll
        for (int j = 0; j < TN; j++) acc[i][j] = 0.f;

    for (int k0 = 0; k0 < K; k0 += BK) {
        #pragma unroll
        for (int i = tid; i < BM * BK; i += 256) {
            int m = i / BK, kk = i % BK;
            int gm = row0 + m;
            As[kk][m] = (gm < M) ? A[(size_t)gm * K + k0 + kk] : 0.f;
        }
        #pragma unroll
        for (int i = tid; i < BK * BN; i += 256) {
            int kk = i / BN, n = i % BN;
            Bs[kk][n] = B[(size_t)(k0 + kk) * Nc + col0 + n];
        }
        __syncthreads();
        #pragma unroll
        for (int kk = 0; kk < BK; kk++) {
            float ra[TM], rb[TN];
            #pragma unroll
            for (int i = 0; i < TM; i++) ra[i] = As[kk][ty * TM + i];
            #pragma unroll
            for (int j = 0; j < TN; j++) rb[j] = Bs[kk][tx * TN + j];
            #pragma unroll
            for (int i = 0; i < TM; i++)
                #pragma unroll
                for (int j = 0; j < TN; j++)
                    acc[i][j] += ra[i] * rb[j];
        }
        __syncthreads();
    }

    #pragma unroll
    for (int i = 0; i < TM; i++) {
        int gm = row0 + ty * TM + i;
        if (gm >= M) continue;
        #pragma unroll
        for (int j = 0; j < TN; j++) {
            int gn = col0 + tx * TN + j;
            float cval = acc[i][j] + bias[gn];
            if (relu) cval = fmaxf(cval, 0.f);
            C[(size_t)gm * Nc + gn] = cval;
        }
    }
}

// ---------------- fused attention + head-mean + skip + residual + LN -------
// One warp per destination node. Online softmax over its CSR edge list.
__global__ void attn_kernel(const float* __restrict__ q,
                            const float* __restrict__ k,
                            const float* __restrict__ v,
                            const float* __restrict__ skip,
                            const float* __restrict__ hprev,
                            const float* __restrict__ ln_g,
                            const float* __restrict__ ln_b,
                            float* __restrict__ hout)
{
    int gw = (blockIdx.x * blockDim.x + threadIdx.x) >> 5;
    int lane = threadIdx.x & 31;
    if (gw >= NN) return;
    int n = gw;

    float4 qreg[HEADS];
    const float4* qp = reinterpret_cast<const float4*>(q + (size_t)n * QKVD);
    #pragma unroll
    for (int h = 0; h < HEADS; h++) qreg[h] = qp[h * 32 + lane];

    const float NEG_INF = __int_as_float(0xff800000u);
    float m[HEADS], l[HEADS], acc[HEADS][4];
    #pragma unroll
    for (int h = 0; h < HEADS; h++) {
        m[h] = NEG_INF; l[h] = 0.f;
        acc[h][0] = acc[h][1] = acc[h][2] = acc[h][3] = 0.f;
    }

    int beg = g_rowptr[n], end = g_rowptr[n + 1];
    const float scale = 0.0883883476483184f;  // 1/sqrt(128)

    for (int e = beg; e < end; e++) {
        int s = g_col[e];
        const float4* kp = reinterpret_cast<const float4*>(k + (size_t)s * QKVD);
        const float4* vp = reinterpret_cast<const float4*>(v + (size_t)s * QKVD);
        #pragma unroll
        for (int h = 0; h < HEADS; h++) {
            float4 kk = kp[h * 32 + lane];
            float part = qreg[h].x * kk.x + qreg[h].y * kk.y
                       + qreg[h].z * kk.z + qreg[h].w * kk.w;
            #pragma unroll
            for (int o = 16; o > 0; o >>= 1)
                part += __shfl_xor_sync(0xffffffffu, part, o);
            float sc = part * scale;
            float mn = fmaxf(m[h], sc);
            float corr = __expf(m[h] - mn);
            float p    = __expf(sc   - mn);
            float4 vv = vp[h * 32 + lane];
            acc[h][0] = acc[h][0] * corr + p * vv.x;
            acc[h][1] = acc[h][1] * corr + p * vv.y;
            acc[h][2] = acc[h][2] * corr + p * vv.z;
            acc[h][3] = acc[h][3] * corr + p * vv.w;
            l[h] = l[h] * corr + p;
            m[h] = mn;
        }
    }

    // head mean
    float r[4];
    #pragma unroll
    for (int j = 0; j < 4; j++) {
        float t = 0.f;
        #pragma unroll
        for (int h = 0; h < HEADS; h++) t += acc[h][j] / (l[h] + 1e-16f);
        r[j] = t * 0.25f;
    }

    // + skip projection + residual
    float4 sk = reinterpret_cast<const float4*>(skip  + (size_t)n * HIDD)[lane];
    float4 hp = reinterpret_cast<const float4*>(hprev + (size_t)n * HIDD)[lane];
    r[0] += sk.x + hp.x; r[1] += sk.y + hp.y;
    r[2] += sk.z + hp.z; r[3] += sk.w + hp.w;

    // LayerNorm over 128
    float sum = r[0] + r[1] + r[2] + r[3];
    #pragma unroll
    for (int o = 16; o > 0; o >>= 1) sum += __shfl_xor_sync(0xffffffffu, sum, o);
    float mean = sum * (1.f / 128.f);
    float c0 = r[0] - mean, c1 = r[1] - mean, c2 = r[2] - mean, c3 = r[3] - mean;
    float vs = c0 * c0 + c1 * c1 + c2 * c2 + c3 * c3;
    #pragma unroll
    for (int o = 16; o > 0; o >>= 1) vs += __shfl_xor_sync(0xffffffffu, vs, o);
    float inv = rsqrtf(vs * (1.f / 128.f) + 1e-5f);

    float4 gg = reinterpret_cast<const float4*>(ln_g)[lane];
    float4 bb = reinterpret_cast<const float4*>(ln_b)[lane];
    float4 outv;
    outv.x = c0 * inv * gg.x + bb.x;
    outv.y = c1 * inv * gg.y + bb.y;
    outv.z = c2 * inv * gg.z + bb.z;
    outv.w = c3 * inv * gg.w + bb.w;
    reinterpret_cast<float4*>(hout + (size_t)n * HIDD)[lane] = outv;
}

// ---------------- launch ---------------------------------------------------
static inline float* sym(const void* symbol) {
    void* p = nullptr;
    cudaGetSymbolAddress(&p, symbol);
    return (float*)p;
}

extern "C" void kernel_launch(void* const* d_in, const int* in_sizes, int n_in,
                              void* d_out, int out_size)
{
    const float* x     = (const float*)d_in[0];
    const int*   ei    = (const int*)  d_in[1];
    const float* lin_w = (const float*)d_in[2];
    const float* lin_b = (const float*)d_in[3];
    // layer param base indices
    const int L1 = 4, L2 = 14;

    float* h  = sym(g_h);
    float* h2 = sym(g_h2);
    float* q  = sym(g_q);
    float* k  = sym(g_k);
    float* v  = sym(g_v);
    float* s  = sym(g_s);

    dim3 blk(256);
    // input projection: h = relu(x @ lin_w + lin_b)
    {
        dim3 grid(HIDD / 64, (NN + 63) / 64);
        gemm_kernel<64, 64, 16, 4, 4><<<grid, blk>>>(x, lin_w, lin_b, h,
                                                     NN, HIDD, INDIM, 1);
    }
    // CSR build
    init_kernel<<<(NN + 255) / 256, blk>>>();
    count_kernel<<<(EE + 255) / 256, blk>>>(ei);
    scan_kernel<<<1, 1024>>>();
    scatter_kernel<<<(EE + 255) / 256, blk>>>(ei);

    const float* hin = h;
    for (int layer = 0; layer < 2; layer++) {
        int base = (layer == 0) ? L1 : L2;
        const float* qw = (const float*)d_in[base + 0];
        const float* qb = (const float*)d_in[base + 1];
        const float* kw = (const float*)d_in[base + 2];
        const float* kb = (const float*)d_in[base + 3];
        const float* vw = (const float*)d_in[base + 4];
        const float* vb = (const float*)d_in[base + 5];
        const float* sw = (const float*)d_in[base + 6];
        const float* sb = (const float*)d_in[base + 7];
        const float* lg = (const float*)d_in[base + 8];
        const float* lb = (const float*)d_in[base + 9];

        dim3 gqkv(QKVD / 64, (NN + 63) / 64);
        gemm_kernel<64, 64, 16, 4, 4><<<gqkv, blk>>>(hin, qw, qb, q, NN, QKVD, HIDD, 0);
        gemm_kernel<64, 64, 16, 4, 4><<<gqkv, blk>>>(hin, kw, kb, k, NN, QKVD, HIDD, 0);
        gemm_kernel<64, 64, 16, 4, 4><<<gqkv, blk>>>(hin, vw, vb, v, NN, QKVD, HIDD, 0);
        dim3 gs(HIDD / 64, (NN + 63) / 64);
        gemm_kernel<64, 64, 16, 4, 4><<<gs, blk>>>(hin, sw, sb, s, NN, HIDD, HIDD, 0);

        float* out = (layer == 0) ? h2 : (float*)d_out;
        int warps_per_block = 256 / 32;
        dim3 ga((NN + warps_per_block - 1) / warps_per_block);
        attn_kernel<<<ga, blk>>>(q, k, v, s, hin, lg, lb, out);
        hin = h2;
    }
}

// round 2
// speedup vs baseline: 2.3335x; 2.3335x over previous
#include <cuda_runtime.h>
#include <math.h>
#include <stdint.h>

#define NN   20000
#define EE   160000
#define HIDD 128
#define HEADS 4
#define QKVD (HEADS*HIDD)   // 512
#define INDIM 256

// ---------------- scratch (device globals; no allocation allowed) ----------
__device__ float g_h [NN*HIDD];     // hidden in
__device__ float g_h2[NN*HIDD];     // hidden out of layer1
__device__ float g_q [NN*QKVD];
__device__ float g_k [NN*QKVD];
__device__ float g_v [NN*QKVD];
__device__ float g_s [NN*HIDD];     // skip projection
__device__ int   g_deg[NN];
__device__ int   g_cursor[NN];
__device__ int   g_rowptr[NN+1];
__device__ int   g_col[EE];         // src node per CSR slot (sorted by dst)

// ---------------- CSR build ------------------------------------------------
__global__ void init_kernel() {
    int i = blockIdx.x * blockDim.x + threadIdx.x;
    if (i < NN) { g_deg[i] = 0; g_cursor[i] = 0; }
}

__global__ void count_kernel(const int* __restrict__ ei) {
    int e = blockIdx.x * blockDim.x + threadIdx.x;
    if (e < EE) atomicAdd(&g_deg[ei[EE + e]], 1);   // dst = ei[1][e]
}

// single-block exclusive scan of g_deg -> g_rowptr
__global__ void scan_kernel() {
    const int T = 1024;
    const int CH = (NN + T - 1) / T;  // 20
    int t = threadIdx.x;
    int lane = t & 31, wid = t >> 5;
    int vals[CH];
    int base = t * CH;
    int s = 0;
    #pragma unroll
    for (int i = 0; i < CH; i++) {
        int idx = base + i;
        int d = (idx < NN) ? g_deg[idx] : 0;
        vals[i] = d; s += d;
    }
    int x = s;
    #pragma unroll
    for (int o = 1; o < 32; o <<= 1) {
        int y = __shfl_up_sync(0xffffffffu, x, o);
        if (lane >= o) x += y;
    }
    __shared__ int wsum[32];
    if (lane == 31) wsum[wid] = x;
    __syncthreads();
    if (wid == 0) {
        int w = wsum[lane];
        #pragma unroll
        for (int o = 1; o < 32; o <<= 1) {
            int y = __shfl_up_sync(0xffffffffu, w, o);
            if (lane >= o) w += y;
        }
        wsum[lane] = w;
    }
    __syncthreads();
    int excl = x - s + ((wid > 0) ? wsum[wid - 1] : 0);
    int off = excl;
    #pragma unroll
    for (int i = 0; i < CH; i++) {
        int idx = base + i;
        if (idx < NN) g_rowptr[idx] = off;
        off += vals[i];
    }
    if (t == T - 1) g_rowptr[NN] = off;
}

__global__ void scatter_kernel(const int* __restrict__ ei) {
    int e = blockIdx.x * blockDim.x + threadIdx.x;
    if (e < EE) {
        int d = ei[EE + e];
        int pos = atomicAdd(&g_cursor[d], 1);
        g_col[g_rowptr[d] + pos] = ei[e];
    }
}

// ---------------- TF32 tensor-core GEMM ------------------------------------
// C[mat] = A[M,K] @ B[mat][K,Nc] + bias (optional relu). Up to 4 output
// matrices fused in one launch via col-block -> matrix mapping.

__device__ __forceinline__ uint32_t f2tf32(float x) {
    uint32_t r;
    asm("cvt.rna.tf32.f32 %0, %1;" : "=r"(r) : "f"(x));
    return r;
}

__device__ __forceinline__ void mma_tf32(float c[4],
                                         const uint32_t a[4],
                                         const uint32_t b[2]) {
    asm volatile(
        "mma.sync.aligned.m16n8k8.row.col.f32.tf32.tf32.f32 "
        "{%0,%1,%2,%3}, {%4,%5,%6,%7}, {%8,%9}, {%0,%1,%2,%3};"
        : "+f"(c[0]), "+f"(c[1]), "+f"(c[2]), "+f"(c[3])
        : "r"(a[0]), "r"(a[1]), "r"(a[2]), "r"(a[3]),
          "r"(b[0]), "r"(b[1]));
}

struct GemmArgs {
    const float* A;
    const float* B[4];
    const float* bias[4];
    float*       C[4];
    int Ncols[4];
    int units[4];   // Ncols/64 per matrix (0 if unused)
    int K;
    int M;
    int relu;
};

// BM=128, BN=64, BK=32, 8 warps (4 x 2), warp tile 32x32
__global__ void __launch_bounds__(256, 2) tf32_gemm(GemmArgs ga)
{
    // col-block -> (matrix, local col block)
    int cb = blockIdx.x;
    int mat = 0;
    while (mat < 3 && cb >= ga.units[mat]) { cb -= ga.units[mat]; mat++; }
    const float* __restrict__ B    = ga.B[mat];
    const float* __restrict__ bias = ga.bias[mat];
    float*       __restrict__ C    = ga.C[mat];
    const int Nc   = ga.Ncols[mat];
    const int col0 = cb * 64;
    const int row0 = blockIdx.y * 128;
    const int K = ga.K;
    const int M = ga.M;

    __shared__ uint32_t As[128][36];   // pad 36 -> conflict-free frags
    __shared__ uint32_t Bs[32][72];    // pad 72 -> conflict-free frags

    const int tid   = threadIdx.x;
    const int warp  = tid >> 5;
    const int lane  = tid & 31;
    const int group = lane >> 2;
    const int tig   = lane & 3;
    const int wm = warp >> 1;          // 0..3
    const int wn = warp & 1;           // 0..1
    const int wrow = wm * 32;
    const int wcol = wn * 32;

    float acc[2][4][4];
    #pragma unroll
    for (int mt = 0; mt < 2; mt++)
        #pragma unroll
        for (int nt = 0; nt < 4; nt++)
            #pragma unroll
            for (int r = 0; r < 4; r++) acc[mt][nt][r] = 0.f;

    for (int k0 = 0; k0 < K; k0 += 32) {
        // A tile: 128 rows x 32 cols = 1024 float4 loads; 4 per thread
        #pragma unroll
        for (int it = 0; it < 4; it++) {
            int idx = tid + it * 256;
            int r  = idx >> 3;
            int c4 = (idx & 7) * 4;
            int gm = row0 + r;
            float4 val = make_float4(0.f, 0.f, 0.f, 0.f);
            if (gm < M)
                val = *reinterpret_cast<const float4*>(ga.A + (size_t)gm * K + k0 + c4);
            As[r][c4 + 0] = f2tf32(val.x);
            As[r][c4 + 1] = f2tf32(val.y);
            As[r][c4 + 2] = f2tf32(val.z);
            As[r][c4 + 3] = f2tf32(val.w);
        }
        // B tile: 32 rows x 64 cols = 512 float4; 2 per thread
        #pragma unroll
        for (int it = 0; it < 2; it++) {
            int idx = tid + it * 256;
            int r  = idx >> 4;
            int c4 = (idx & 15) * 4;
            float4 val = *reinterpret_cast<const float4*>(
                B + (size_t)(k0 + r) * Nc + col0 + c4);
            Bs[r][c4 + 0] = f2tf32(val.x);
            Bs[r][c4 + 1] = f2tf32(val.y);
            Bs[r][c4 + 2] = f2tf32(val.z);
            Bs[r][c4 + 3] = f2tf32(val.w);
        }
        __syncthreads();

        #pragma unroll
        for (int ks = 0; ks < 32; ks += 8) {
            uint32_t af[2][4], bf[4][2];
            #pragma unroll
            for (int mt = 0; mt < 2; mt++) {
                int rb = wrow + mt * 16 + group;
                af[mt][0] = As[rb][ks + tig];
                af[mt][1] = As[rb + 8][ks + tig];
                af[mt][2] = As[rb][ks + tig + 4];
                af[mt][3] = As[rb + 8][ks + tig + 4];
            }
            #pragma unroll
            for (int nt = 0; nt < 4; nt++) {
                int cbse = wcol + nt * 8 + group;
                bf[nt][0] = Bs[ks + tig][cbse];
                bf[nt][1] = Bs[ks + tig + 4][cbse];
            }
            #pragma unroll
            for (int mt = 0; mt < 2; mt++)
                #pragma unroll
                for (int nt = 0; nt < 4; nt++)
                    mma_tf32(acc[mt][nt], af[mt], bf[nt]);
        }
        __syncthreads();
    }

    // epilogue: + bias, optional relu
    #pragma unroll
    for (int mt = 0; mt < 2; mt++) {
        int gr0 = row0 + wrow + mt * 16 + group;
        int gr1 = gr0 + 8;
        #pragma unroll
        for (int nt = 0; nt < 4; nt++) {
            int gc = col0 + wcol + nt * 8 + tig * 2;
            float b0 = bias[gc], b1 = bias[gc + 1];
            float v0 = acc[mt][nt][0] + b0;
            float v1 = acc[mt][nt][1] + b1;
            float v2 = acc[mt][nt][2] + b0;
            float v3 = acc[mt][nt][3] + b1;
            if (ga.relu) {
                v0 = fmaxf(v0, 0.f); v1 = fmaxf(v1, 0.f);
                v2 = fmaxf(v2, 0.f); v3 = fmaxf(v3, 0.f);
            }
            if (gr0 < M) {
                C[(size_t)gr0 * Nc + gc]     = v0;
                C[(size_t)gr0 * Nc + gc + 1] = v1;
            }
            if (gr1 < M) {
                C[(size_t)gr1 * Nc + gc]     = v2;
                C[(size_t)gr1 * Nc + gc + 1] = v3;
            }
        }
    }
}

// ---------------- fused attention + head-mean + skip + residual + LN -------
__global__ void attn_kernel(const float* __restrict__ q,
                            const float* __restrict__ k,
                            const float* __restrict__ v,
                            const float* __restrict__ skip,
                            const float* __restrict__ hprev,
                            const float* __restrict__ ln_g,
                            const float* __restrict__ ln_b,
                            float* __restrict__ hout)
{
    int gw = (blockIdx.x * blockDim.x + threadIdx.x) >> 5;
    int lane = threadIdx.x & 31;
    if (gw >= NN) return;
    int n = gw;

    float4 qreg[HEADS];
    const float4* qp = reinterpret_cast<const float4*>(q + (size_t)n * QKVD);
    #pragma unroll
    for (int h = 0; h < HEADS; h++) qreg[h] = qp[h * 32 + lane];

    const float NEG_INF = __int_as_float(0xff800000u);
    float m[HEADS], l[HEADS], acc[HEADS][4];
    #pragma unroll
    for (int h = 0; h < HEADS; h++) {
        m[h] = NEG_INF; l[h] = 0.f;
        acc[h][0] = acc[h][1] = acc[h][2] = acc[h][3] = 0.f;
    }

    int beg = g_rowptr[n], end = g_rowptr[n + 1];
    const float scale = 0.0883883476483184f;  // 1/sqrt(128)

    for (int e = beg; e < end; e++) {
        int s = g_col[e];
        const float4* kp = reinterpret_cast<const float4*>(k + (size_t)s * QKVD);
        const float4* vp = reinterpret_cast<const float4*>(v + (size_t)s * QKVD);
        #pragma unroll
        for (int h = 0; h < HEADS; h++) {
            float4 kk = kp[h * 32 + lane];
            float part = qreg[h].x * kk.x + qreg[h].y * kk.y
                       + qreg[h].z * kk.z + qreg[h].w * kk.w;
            #pragma unroll
            for (int o = 16; o > 0; o >>= 1)
                part += __shfl_xor_sync(0xffffffffu, part, o);
            float sc = part * scale;
            float mn = fmaxf(m[h], sc);
            float corr = __expf(m[h] - mn);
            float p    = __expf(sc   - mn);
            float4 vv = vp[h * 32 + lane];
            acc[h][0] = acc[h][0] * corr + p * vv.x;
            acc[h][1] = acc[h][1] * corr + p * vv.y;
            acc[h][2] = acc[h][2] * corr + p * vv.z;
            acc[h][3] = acc[h][3] * corr + p * vv.w;
            l[h] = l[h] * corr + p;
            m[h] = mn;
        }
    }

    float r[4];
    #pragma unroll
    for (int j = 0; j < 4; j++) {
        float t = 0.f;
        #pragma unroll
        for (int h = 0; h < HEADS; h++) t += acc[h][j] / (l[h] + 1e-16f);
        r[j] = t * 0.25f;
    }

    float4 sk = reinterpret_cast<const float4*>(skip  + (size_t)n * HIDD)[lane];
    float4 hp = reinterpret_cast<const float4*>(hprev + (size_t)n * HIDD)[lane];
    r[0] += sk.x + hp.x; r[1] += sk.y + hp.y;
    r[2] += sk.z + hp.z; r[3] += sk.w + hp.w;

    float sum = r[0] + r[1] + r[2] + r[3];
    #pragma unroll
    for (int o = 16; o > 0; o >>= 1) sum += __shfl_xor_sync(0xffffffffu, sum, o);
    float mean = sum * (1.f / 128.f);
    float c0 = r[0] - mean, c1 = r[1] - mean, c2 = r[2] - mean, c3 = r[3] - mean;
    float vs = c0 * c0 + c1 * c1 + c2 * c2 + c3 * c3;
    #pragma unroll
    for (int o = 16; o > 0; o >>= 1) vs += __shfl_xor_sync(0xffffffffu, vs, o);
    float inv = rsqrtf(vs * (1.f / 128.f) + 1e-5f);

    float4 gg = reinterpret_cast<const float4*>(ln_g)[lane];
    float4 bb = reinterpret_cast<const float4*>(ln_b)[lane];
    float4 outv;
    outv.x = c0 * inv * gg.x + bb.x;
    outv.y = c1 * inv * gg.y + bb.y;
    outv.z = c2 * inv * gg.z + bb.z;
    outv.w = c3 * inv * gg.w + bb.w;
    reinterpret_cast<float4*>(hout + (size_t)n * HIDD)[lane] = outv;
}

// ---------------- launch ---------------------------------------------------
static inline float* sym(const void* symbol) {
    void* p = nullptr;
    cudaGetSymbolAddress(&p, symbol);
    return (float*)p;
}

extern "C" void kernel_launch(void* const* d_in, const int* in_sizes, int n_in,
                              void* d_out, int out_size)
{
    const float* x     = (const float*)d_in[0];
    const int*   ei    = (const int*)  d_in[1];
    const float* lin_w = (const float*)d_in[2];
    const float* lin_b = (const float*)d_in[3];
    const int L1 = 4, L2 = 14;

    float* h  = sym(g_h);
    float* h2 = sym(g_h2);
    float* q  = sym(g_q);
    float* k  = sym(g_k);
    float* v  = sym(g_v);
    float* s  = sym(g_s);

    dim3 blk(256);
    const int rowBlocks = (NN + 127) / 128;   // 157

    // input projection: h = relu(x @ lin_w + lin_b)
    {
        GemmArgs ga = {};
        ga.A = x;
        ga.B[0] = lin_w;  ga.bias[0] = lin_b;  ga.C[0] = h;
        ga.Ncols[0] = HIDD; ga.units[0] = HIDD / 64;  // 2
        ga.K = INDIM; ga.M = NN; ga.relu = 1;
        dim3 grid(ga.units[0], rowBlocks);
        tf32_gemm<<<grid, blk>>>(ga);
    }

    // CSR build
    init_kernel<<<(NN + 255) / 256, blk>>>();
    count_kernel<<<(EE + 255) / 256, blk>>>(ei);
    scan_kernel<<<1, 1024>>>();
    scatter_kernel<<<(EE + 255) / 256, blk>>>(ei);

    const float* hin = h;
    for (int layer = 0; layer < 2; layer++) {
        int base = (layer == 0) ? L1 : L2;
        const float* qw = (const float*)d_in[base + 0];
        const float* qb = (const float*)d_in[base + 1];
        const float* kw = (const float*)d_in[base + 2];
        const float* kb = (const float*)d_in[base + 3];
        const float* vw = (const float*)d_in[base + 4];
        const float* vb = (const float*)d_in[base + 5];
        const float* sw = (const float*)d_in[base + 6];
        const float* sb = (const float*)d_in[base + 7];
        const float* lg = (const float*)d_in[base + 8];
        const float* lb = (const float*)d_in[base + 9];

        // fused Q,K,V,S GEMM
        GemmArgs ga = {};
        ga.A = hin;
        ga.B[0] = qw; ga.bias[0] = qb; ga.C[0] = q; ga.Ncols[0] = QKVD; ga.units[0] = QKVD / 64; // 8
        ga.B[1] = kw; ga.bias[1] = kb; ga.C[1] = k; ga.Ncols[1] = QKVD; ga.units[1] = QKVD / 64; // 8
        ga.B[2] = vw; ga.bias[2] = vb; ga.C[2] = v; ga.Ncols[2] = QKVD; ga.units[2] = QKVD / 64; // 8
        ga.B[3] = sw; ga.bias[3] = sb; ga.C[3] = s; ga.Ncols[3] = HIDD; ga.units[3] = HIDD / 64; // 2
        ga.K = HIDD; ga.M = NN; ga.relu = 0;
        int totalUnits = ga.units[0] + ga.units[1] + ga.units[2] + ga.units[3];  // 26
        dim3 grid(totalUnits, rowBlocks);
        tf32_gemm<<<grid, blk>>>(ga);

        float* out = (layer == 0) ? h2 : (float*)d_out;
        dim3 gatt((NN + 7) / 8);
        attn_kernel<<<gatt, blk>>>(q, k, v, s, hin, lg, lb, out);
        hin = h2;
    }
}

// round 3
// speedup vs baseline: 2.3915x; 1.0249x over previous
#include <cuda_runtime.h>
#include <math.h>
#include <stdint.h>

#define NN   20000
#define EE   160000
#define HIDD 128
#define HEADS 4
#define QKVD (HEADS*HIDD)   // 512
#define INDIM 256
#define NB   ((NN + 255) / 256)   // 79 scan blocks

// ---------------- scratch (device globals; no allocation allowed) ----------
__device__ float g_h [NN*HIDD];
__device__ float g_h2[NN*HIDD];
__device__ float g_q [NN*QKVD];
__device__ float g_k [NN*QKVD];
__device__ float g_v [NN*QKVD];
__device__ float g_s [NN*HIDD];
__device__ int   g_deg[NN];
__device__ int   g_cursor[NN];
__device__ int   g_rowptr[NN+1];
__device__ int   g_col[EE];
__device__ int   g_bsum[NB];
__device__ int   g_boff[NB];

// ---------------- CSR build ------------------------------------------------
__global__ void init_kernel() {
    int i = blockIdx.x * blockDim.x + threadIdx.x;
    if (i < NN) { g_deg[i] = 0; g_cursor[i] = 0; }
}

__global__ void count_kernel(const int* __restrict__ ei) {
    int e = blockIdx.x * blockDim.x + threadIdx.x;
    if (e < EE) atomicAdd(&g_deg[ei[EE + e]], 1);
}

// per-block sums of g_deg (coalesced)
__global__ void block_sum_kernel() {
    int tid = threadIdx.x;
    int i = blockIdx.x * 256 + tid;
    int d = (i < NN) ? g_deg[i] : 0;
    int lane = tid & 31, wid = tid >> 5;
    int x = d;
    #pragma unroll
    for (int o = 16; o > 0; o >>= 1) x += __shfl_xor_sync(0xffffffffu, x, o);
    __shared__ int ws[8];
    if (lane == 0) ws[wid] = x;
    __syncthreads();
    if (wid == 0) {
        int v = (lane < 8) ? ws[lane] : 0;
        #pragma unroll
        for (int o = 4; o > 0; o >>= 1) v += __shfl_xor_sync(0xffffffffu, v, o);
        if (lane == 0) g_bsum[blockIdx.x] = v;
    }
}

// scan the NB block sums (1 block, 128 threads)
__global__ void bsum_scan_kernel() {
    int t = threadIdx.x;
    int lane = t & 31, wid = t >> 5;
    int v = (t < NB) ? g_bsum[t] : 0;
    int x = v;
    #pragma unroll
    for (int o = 1; o < 32; o <<= 1) {
        int y = __shfl_up_sync(0xffffffffu, x, o);
        if (lane >= o) x += y;
    }
    __shared__ int ws[4];
    if (lane == 31) ws[wid] = x;
    __syncthreads();
    if (wid == 0 && lane < 4) {
        int w = ws[lane];
        #pragma unroll
        for (int o = 1; o < 4; o <<= 1) {
            int y = __shfl_up_sync(0x0000000fu, w, o);
            if (lane >= o) w += y;
        }
        ws[lane] = w;
    }
    __syncthreads();
    int incl = x + ((wid > 0) ? ws[wid - 1] : 0);
    if (t < NB) g_boff[t] = incl - v;
    if (t == 127) g_rowptr[NN] = incl;   // == EE
}

// per-block exclusive scan + block offset -> rowptr (coalesced)
__global__ void rowptr_kernel() {
    int tid = threadIdx.x;
    int i = blockIdx.x * 256 + tid;
    int d = (i < NN) ? g_deg[i] : 0;
    int lane = tid & 31, wid = tid >> 5;
    int x = d;
    #pragma unroll
    for (int o = 1; o < 32; o <<= 1) {
        int y = __shfl_up_sync(0xffffffffu, x, o);
        if (lane >= o) x += y;
    }
    __shared__ int ws[8];
    if (lane == 31) ws[wid] = x;
    __syncthreads();
    if (wid == 0 && lane < 8) {
        int w = ws[lane];
        #pragma unroll
        for (int o = 1; o < 8; o <<= 1) {
            int y = __shfl_up_sync(0x000000ffu, w, o);
            if (lane >= o) w += y;
        }
        ws[lane] = w;
    }
    __syncthreads();
    int excl = x - d + ((wid > 0) ? ws[wid - 1] : 0) + g_boff[blockIdx.x];
    if (i < NN) g_rowptr[i] = excl;
}

__global__ void scatter_kernel(const int* __restrict__ ei) {
    int e = blockIdx.x * blockDim.x + threadIdx.x;
    if (e < EE) {
        int d = ei[EE + e];
        int pos = atomicAdd(&g_cursor[d], 1);
        g_col[g_rowptr[d] + pos] = ei[e];
    }
}

// ---------------- TF32 tensor-core GEMM (pipelined, vectorized frags) ------
__device__ __forceinline__ uint32_t f2tf32(float x) {
    uint32_t r;
    asm("cvt.rna.tf32.f32 %0, %1;" : "=r"(r) : "f"(x));
    return r;
}

__device__ __forceinline__ void mma_tf32(float c[4],
                                         const uint32_t a[4],
                                         const uint32_t b[2]) {
    asm volatile(
        "mma.sync.aligned.m16n8k8.row.col.f32.tf32.tf32.f32 "
        "{%0,%1,%2,%3}, {%4,%5,%6,%7}, {%8,%9}, {%0,%1,%2,%3};"
        : "+f"(c[0]), "+f"(c[1]), "+f"(c[2]), "+f"(c[3])
        : "r"(a[0]), "r"(a[1]), "r"(a[2]), "r"(a[3]),
          "r"(b[0]), "r"(b[1]));
}

struct GemmArgs {
    const float* A;
    const float* B[4];
    const float* bias[4];
    float*       C[4];
    int Ncols[4];
    int units[4];
    int K;
    int M;
    int relu;
};

// smem word layout (dynamic):
//   A: [buf 2][ktile 4][mtile 8][lane 32][reg 4]  -> 2*4096 words
//   B: [buf 2][row 32][72]                        -> 2*2304 words
#define A_WORDS 4096
#define B_WORDS 2304
#define B_BASE  (2 * A_WORDS)
#define SMEM_WORDS (2 * A_WORDS + 2 * B_WORDS)

// BM=128, BN=64, BK=32, 8 warps (4x2), warp tile 32x32
__global__ void __launch_bounds__(256, 2) tf32_gemm(GemmArgs ga)
{
    extern __shared__ uint32_t sh[];

    int cb = blockIdx.x;
    int mat = 0;
    while (mat < 3 && cb >= ga.units[mat]) { cb -= ga.units[mat]; mat++; }
    const float* __restrict__ B    = ga.B[mat];
    const float* __restrict__ bias = ga.bias[mat];
    float*       __restrict__ C    = ga.C[mat];
    const int Nc   = ga.Ncols[mat];
    const int col0 = cb * 64;
    const int row0 = blockIdx.y * 128;
    const int K = ga.K;
    const int M = ga.M;
    const int iters = K >> 5;

    const int tid   = threadIdx.x;
    const int warp  = tid >> 5;
    const int lane  = tid & 31;
    const int group = lane >> 2;
    const int tig   = lane & 3;
    const int wm = warp >> 1;
    const int wn = warp & 1;
    const int wcol = wn * 32;

    // staging registers
    float4 aReg[4], bReg[2];
    // precomputed per-thread load/store coords
    int ar[4], ac4[4];
    #pragma unroll
    for (int it = 0; it < 4; it++) {
        int idx = tid + it * 256;
        ar[it] = idx >> 3; ac4[it] = (idx & 7) * 4;
    }
    int br[2], bc4[2];
    #pragma unroll
    for (int it = 0; it < 2; it++) {
        int idx = tid + it * 256;
        br[it] = idx >> 4; bc4[it] = (idx & 15) * 4;
    }

    float acc[2][4][4];
    #pragma unroll
    for (int mt = 0; mt < 2; mt++)
        #pragma unroll
        for (int nt = 0; nt < 4; nt++)
            #pragma unroll
            for (int r = 0; r < 4; r++) acc[mt][nt][r] = 0.f;

    // ---- load tile `t` from gmem into staging regs
    auto load_regs = [&](int t) {
        int kk = t << 5;
        #pragma unroll
        for (int it = 0; it < 4; it++) {
            int gm = row0 + ar[it];
            if (gm < M)
                aReg[it] = *reinterpret_cast<const float4*>(
                    ga.A + (size_t)gm * K + kk + ac4[it]);
            else
                aReg[it] = make_float4(0.f, 0.f, 0.f, 0.f);
        }
        #pragma unroll
        for (int it = 0; it < 2; it++)
            bReg[it] = *reinterpret_cast<const float4*>(
                B + (size_t)(kk + br[it]) * Nc + col0 + bc4[it]);
    };

    // ---- convert + store staging regs into smem buffer `buf`
    auto store_smem = [&](int buf) {
        uint32_t* ab = sh + buf * A_WORDS;
        #pragma unroll
        for (int it = 0; it < 4; it++) {
            int r = ar[it], c4 = ac4[it];
            int ktile = c4 >> 3;
            int reg = ((r >> 3) & 1) + 2 * ((c4 >> 2) & 1);
            uint32_t* p = ab + ((ktile * 8 + (r >> 4)) * 32) * 4 + reg;
            int lb = (r & 7) * 4;
            p[(lb + (0 ^ ktile)) * 4] = f2tf32(aReg[it].x);
            p[(lb + (1 ^ ktile)) * 4] = f2tf32(aReg[it].y);
            p[(lb + (2 ^ ktile)) * 4] = f2tf32(aReg[it].z);
            p[(lb + (3 ^ ktile)) * 4] = f2tf32(aReg[it].w);
        }
        uint32_t* bb = sh + B_BASE + buf * B_WORDS;
        #pragma unroll
        for (int it = 0; it < 2; it++) {
            int r = br[it], c4 = bc4[it];
            uint32_t* p = bb + r * 72 + c4;
            p[0] = f2tf32(bReg[it].x);
            p[1] = f2tf32(bReg[it].y);
            p[2] = f2tf32(bReg[it].z);
            p[3] = f2tf32(bReg[it].w);
        }
    };

    // ---- compute one K-tile from smem buffer `buf`
    auto compute = [&](int buf) {
        const uint32_t* ab = sh + buf * A_WORDS;
        const uint32_t* bb = sh + B_BASE + buf * B_WORDS;
        #pragma unroll
        for (int kt = 0; kt < 4; kt++) {
            uint32_t af[2][4], bf[4][2];
            #pragma unroll
            for (int mt = 0; mt < 2; mt++) {
                int mtile = wm * 2 + mt;
                uint4 av = *reinterpret_cast<const uint4*>(
                    ab + ((kt * 8 + mtile) * 32 + (lane ^ kt)) * 4);
                af[mt][0] = av.x; af[mt][1] = av.y;
                af[mt][2] = av.z; af[mt][3] = av.w;
            }
            #pragma unroll
            for (int nt = 0; nt < 4; nt++) {
                int cbse = wcol + nt * 8 + group;
                bf[nt][0] = bb[(kt * 8 + tig)     * 72 + cbse];
                bf[nt][1] = bb[(kt * 8 + tig + 4) * 72 + cbse];
            }
            #pragma unroll
            for (int mt = 0; mt < 2; mt++)
                #pragma unroll
                for (int nt = 0; nt < 4; nt++)
                    mma_tf32(acc[mt][nt], af[mt], bf[nt]);
        }
    };

    // ---- pipelined main loop
    load_regs(0);
    store_smem(0);
    if (iters > 1) load_regs(1);
    __syncthreads();
    for (int i = 0; i < iters; i++) {
        int cur = i & 1;
        if (i + 1 < iters) store_smem(cur ^ 1);
        if (i + 2 < iters) load_regs(i + 2);
        compute(cur);
        __syncthreads();
    }

    // ---- epilogue
    #pragma unroll
    for (int mt = 0; mt < 2; mt++) {
        int gr0 = row0 + wm * 32 + mt * 16 + group;
        int gr1 = gr0 + 8;
        #pragma unroll
        for (int nt = 0; nt < 4; nt++) {
            int gc = col0 + wcol + nt * 8 + tig * 2;
            float b0 = bias[gc], b1 = bias[gc + 1];
            float v0 = acc[mt][nt][0] + b0;
            float v1 = acc[mt][nt][1] + b1;
            float v2 = acc[mt][nt][2] + b0;
            float v3 = acc[mt][nt][3] + b1;
            if (ga.relu) {
                v0 = fmaxf(v0, 0.f); v1 = fmaxf(v1, 0.f);
                v2 = fmaxf(v2, 0.f); v3 = fmaxf(v3, 0.f);
            }
            if (gr0 < M) {
                C[(size_t)gr0 * Nc + gc]     = v0;
                C[(size_t)gr0 * Nc + gc + 1] = v1;
            }
            if (gr1 < M) {
                C[(size_t)gr1 * Nc + gc]     = v2;
                C[(size_t)gr1 * Nc + gc + 1] = v3;
            }
        }
    }
}

// ---------------- fused attention + head-mean + skip + residual + LN -------
__global__ void attn_kernel(const float* __restrict__ q,
                            const float* __restrict__ k,
                            const float* __restrict__ v,
                            const float* __restrict__ skip,
                            const float* __restrict__ hprev,
                            const float* __restrict__ ln_g,
                            const float* __restrict__ ln_b,
                            float* __restrict__ hout)
{
    int gw = (blockIdx.x * blockDim.x + threadIdx.x) >> 5;
    int lane = threadIdx.x & 31;
    if (gw >= NN) return;
    int n = gw;

    float4 qreg[HEADS];
    const float4* qp = reinterpret_cast<const float4*>(q + (size_t)n * QKVD);
    #pragma unroll
    for (int h = 0; h < HEADS; h++) qreg[h] = qp[h * 32 + lane];

    const float NEG_INF = __int_as_float(0xff800000u);
    float m[HEADS], l[HEADS], acc[HEADS][4];
    #pragma unroll
    for (int h = 0; h < HEADS; h++) {
        m[h] = NEG_INF; l[h] = 0.f;
        acc[h][0] = acc[h][1] = acc[h][2] = acc[h][3] = 0.f;
    }

    int beg = g_rowptr[n], end = g_rowptr[n + 1];
    const float scale = 0.0883883476483184f;  // 1/sqrt(128)

    for (int e = beg; e < end; e++) {
        int s = g_col[e];
        const float4* kp = reinterpret_cast<const float4*>(k + (size_t)s * QKVD);
        const float4* vp = reinterpret_cast<const float4*>(v + (size_t)s * QKVD);
        #pragma unroll
        for (int h = 0; h < HEADS; h++) {
            float4 kk = kp[h * 32 + lane];
            float part = qreg[h].x * kk.x + qreg[h].y * kk.y
                       + qreg[h].z * kk.z + qreg[h].w * kk.w;
            #pragma unroll
            for (int o = 16; o > 0; o >>= 1)
                part += __shfl_xor_sync(0xffffffffu, part, o);
            float sc = part * scale;
            float mn = fmaxf(m[h], sc);
            float corr = __expf(m[h] - mn);
            float p    = __expf(sc   - mn);
            float4 vv = vp[h * 32 + lane];
            acc[h][0] = acc[h][0] * corr + p * vv.x;
            acc[h][1] = acc[h][1] * corr + p * vv.y;
            acc[h][2] = acc[h][2] * corr + p * vv.z;
            acc[h][3] = acc[h][3] * corr + p * vv.w;
            l[h] = l[h] * corr + p;
            m[h] = mn;
        }
    }

    float r[4];
    #pragma unroll
    for (int j = 0; j < 4; j++) {
        float t = 0.f;
        #pragma unroll
        for (int h = 0; h < HEADS; h++) t += acc[h][j] / (l[h] + 1e-16f);
        r[j] = t * 0.25f;
    }

    float4 sk = reinterpret_cast<const float4*>(skip  + (size_t)n * HIDD)[lane];
    float4 hp = reinterpret_cast<const float4*>(hprev + (size_t)n * HIDD)[lane];
    r[0] += sk.x + hp.x; r[1] += sk.y + hp.y;
    r[2] += sk.z + hp.z; r[3] += sk.w + hp.w;

    float sum = r[0] + r[1] + r[2] + r[3];
    #pragma unroll
    for (int o = 16; o > 0; o >>= 1) sum += __shfl_xor_sync(0xffffffffu, sum, o);
    float mean = sum * (1.f / 128.f);
    float c0 = r[0] - mean, c1 = r[1] - mean, c2 = r[2] - mean, c3 = r[3] - mean;
    float vs = c0 * c0 + c1 * c1 + c2 * c2 + c3 * c3;
    #pragma unroll
    for (int o = 16; o > 0; o >>= 1) vs += __shfl_xor_sync(0xffffffffu, vs, o);
    float inv = rsqrtf(vs * (1.f / 128.f) + 1e-5f);

    float4 gg = reinterpret_cast<const float4*>(ln_g)[lane];
    float4 bb = reinterpret_cast<const float4*>(ln_b)[lane];
    float4 outv;
    outv.x = c0 * inv * gg.x + bb.x;
    outv.y = c1 * inv * gg.y + bb.y;
    outv.z = c2 * inv * gg.z + bb.z;
    outv.w = c3 * inv * gg.w + bb.w;
    reinterpret_cast<float4*>(hout + (size_t)n * HIDD)[lane] = outv;
}

// ---------------- launch ---------------------------------------------------
static inline float* sym(const void* symbol) {
    void* p = nullptr;
    cudaGetSymbolAddress(&p, symbol);
    return (float*)p;
}

extern "C" void kernel_launch(void* const* d_in, const int* in_sizes, int n_in,
                              void* d_out, int out_size)
{
    const float* x     = (const float*)d_in[0];
    const int*   ei    = (const int*)  d_in[1];
    const float* lin_w = (const float*)d_in[2];
    const float* lin_b = (const float*)d_in[3];
    const int L1 = 4, L2 = 14;

    float* h  = sym(g_h);
    float* h2 = sym(g_h2);
    float* q  = sym(g_q);
    float* k  = sym(g_k);
    float* v  = sym(g_v);
    float* s  = sym(g_s);

    const int smemBytes = SMEM_WORDS * 4;   // 51200
    cudaFuncSetAttribute(tf32_gemm,
                         cudaFuncAttributeMaxDynamicSharedMemorySize, smemBytes);

    dim3 blk(256);
    const int rowBlocks = (NN + 127) / 128;   // 157

    // input projection: h = relu(x @ lin_w + lin_b)
    {
        GemmArgs ga = {};
        ga.A = x;
        ga.B[0] = lin_w;  ga.bias[0] = lin_b;  ga.C[0] = h;
        ga.Ncols[0] = HIDD; ga.units[0] = HIDD / 64;
        ga.K = INDIM; ga.M = NN; ga.relu = 1;
        dim3 grid(ga.units[0], rowBlocks);
        tf32_gemm<<<grid, blk, smemBytes>>>(ga);
    }

    // CSR build
    init_kernel<<<(NN + 255) / 256, blk>>>();
    count_kernel<<<(EE + 255) / 256, blk>>>(ei);
    block_sum_kernel<<<NB, blk>>>();
    bsum_scan_kernel<<<1, 128>>>();
    rowptr_kernel<<<NB, blk>>>();
    scatter_kernel<<<(EE + 255) / 256, blk>>>(ei);

    const float* hin = h;
    for (int layer = 0; layer < 2; layer++) {
        int base = (layer == 0) ? L1 : L2;
        const float* qw = (const float*)d_in[base + 0];
        const float* qb = (const float*)d_in[base + 1];
        const float* kw = (const float*)d_in[base + 2];
        const float* kb = (const float*)d_in[base + 3];
        const float* vw = (const float*)d_in[base + 4];
        const float* vb = (const float*)d_in[base + 5];
        const float* sw = (const float*)d_in[base + 6];
        const float* sb = (const float*)d_in[base + 7];
        const float* lg = (const float*)d_in[base + 8];
        const float* lb = (const float*)d_in[base + 9];

        GemmArgs ga = {};
        ga.A = hin;
        ga.B[0] = qw; ga.bias[0] = qb; ga.C[0] = q; ga.Ncols[0] = QKVD; ga.units[0] = QKVD / 64;
        ga.B[1] = kw; ga.bias[1] = kb; ga.C[1] = k; ga.Ncols[1] = QKVD; ga.units[1] = QKVD / 64;
        ga.B[2] = vw; ga.bias[2] = vb; ga.C[2] = v; ga.Ncols[2] = QKVD; ga.units[2] = QKVD / 64;
        ga.B[3] = sw; ga.bias[3] = sb; ga.C[3] = s; ga.Ncols[3] = HIDD; ga.units[3] = HIDD / 64;
        ga.K = HIDD; ga.M = NN; ga.relu = 0;
        int totalUnits = ga.units[0] + ga.units[1] + ga.units[2] + ga.units[3];  // 26
        dim3 grid(totalUnits, rowBlocks);
        tf32_gemm<<<grid, blk, smemBytes>>>(ga);

        float* out = (layer == 0) ? h2 : (float*)d_out;
        dim3 gatt((NN + 7) / 8);
        attn_kernel<<<gatt, blk>>>(q, k, v, s, hin, lg, lb, out);
        hin = h2;
    }
}

// round 4
// speedup vs baseline: 2.4962x; 1.0437x over previous
#include <cuda_runtime.h>
#include <math.h>
#include <stdint.h>

#define NN   20000
#define EE   160000
#define HIDD 128
#define HEADS 4
#define QKVD (HEADS*HIDD)   // 512
#define INDIM 256
#define NB   ((NN + 255) / 256)   // 79 scan blocks

// ---------------- scratch (device globals; no allocation allowed) ----------
__device__ float g_h [NN*HIDD];
__device__ float g_h2[NN*HIDD];
__device__ float g_q [NN*QKVD];
__device__ float g_k [NN*QKVD];
__device__ float g_v [NN*QKVD];
__device__ float g_s [NN*HIDD];
__device__ int   g_deg[NN];
__device__ int   g_cursor[NN];
__device__ int   g_rowptr[NN+1];
__device__ int   g_col[EE];
__device__ int   g_bsum[NB];
__device__ int   g_boff[NB];

// ---------------- CSR build ------------------------------------------------
__global__ void init_kernel() {
    int i = blockIdx.x * blockDim.x + threadIdx.x;
    if (i < NN) { g_deg[i] = 0; g_cursor[i] = 0; }
}

__global__ void count_kernel(const int* __restrict__ ei) {
    int e = blockIdx.x * blockDim.x + threadIdx.x;
    if (e < EE) atomicAdd(&g_deg[ei[EE + e]], 1);
}

__global__ void block_sum_kernel() {
    int tid = threadIdx.x;
    int i = blockIdx.x * 256 + tid;
    int d = (i < NN) ? g_deg[i] : 0;
    int lane = tid & 31, wid = tid >> 5;
    int x = d;
    #pragma unroll
    for (int o = 16; o > 0; o >>= 1) x += __shfl_xor_sync(0xffffffffu, x, o);
    __shared__ int ws[8];
    if (lane == 0) ws[wid] = x;
    __syncthreads();
    if (wid == 0) {
        int v = (lane < 8) ? ws[lane] : 0;
        #pragma unroll
        for (int o = 4; o > 0; o >>= 1) v += __shfl_xor_sync(0xffffffffu, v, o);
        if (lane == 0) g_bsum[blockIdx.x] = v;
    }
}

__global__ void bsum_scan_kernel() {
    int t = threadIdx.x;
    int lane = t & 31, wid = t >> 5;
    int v = (t < NB) ? g_bsum[t] : 0;
    int x = v;
    #pragma unroll
    for (int o = 1; o < 32; o <<= 1) {
        int y = __shfl_up_sync(0xffffffffu, x, o);
        if (lane >= o) x += y;
    }
    __shared__ int ws[4];
    if (lane == 31) ws[wid] = x;
    __syncthreads();
    if (wid == 0 && lane < 4) {
        int w = ws[lane];
        #pragma unroll
        for (int o = 1; o < 4; o <<= 1) {
            int y = __shfl_up_sync(0x0000000fu, w, o);
            if (lane >= o) w += y;
        }
        ws[lane] = w;
    }
    __syncthreads();
    int incl = x + ((wid > 0) ? ws[wid - 1] : 0);
    if (t < NB) g_boff[t] = incl - v;
    if (t == 127) g_rowptr[NN] = incl;
}

__global__ void rowptr_kernel() {
    int tid = threadIdx.x;
    int i = blockIdx.x * 256 + tid;
    int d = (i < NN) ? g_deg[i] : 0;
    int lane = tid & 31, wid = tid >> 5;
    int x = d;
    #pragma unroll
    for (int o = 1; o < 32; o <<= 1) {
        int y = __shfl_up_sync(0xffffffffu, x, o);
        if (lane >= o) x += y;
    }
    __shared__ int ws[8];
    if (lane == 31) ws[wid] = x;
    __syncthreads();
    if (wid == 0 && lane < 8) {
        int w = ws[lane];
        #pragma unroll
        for (int o = 1; o < 8; o <<= 1) {
            int y = __shfl_up_sync(0x000000ffu, w, o);
            if (lane >= o) w += y;
        }
        ws[lane] = w;
    }
    __syncthreads();
    int excl = x - d + ((wid > 0) ? ws[wid - 1] : 0) + g_boff[blockIdx.x];
    if (i < NN) g_rowptr[i] = excl;
}

__global__ void scatter_kernel(const int* __restrict__ ei) {
    int e = blockIdx.x * blockDim.x + threadIdx.x;
    if (e < EE) {
        int d = ei[EE + e];
        int pos = atomicAdd(&g_cursor[d], 1);
        g_col[g_rowptr[d] + pos] = ei[e];
    }
}

// ---------------- TF32 tensor-core GEMM ------------------------------------
__device__ __forceinline__ uint32_t f2tf32(float x) {
    uint32_t r;
    asm("cvt.rna.tf32.f32 %0, %1;" : "=r"(r) : "f"(x));
    return r;
}

__device__ __forceinline__ void mma_tf32(float c[4],
                                         const uint32_t a[4],
                                         const uint32_t b[2]) {
    asm volatile(
        "mma.sync.aligned.m16n8k8.row.col.f32.tf32.tf32.f32 "
        "{%0,%1,%2,%3}, {%4,%5,%6,%7}, {%8,%9}, {%0,%1,%2,%3};"
        : "+f"(c[0]), "+f"(c[1]), "+f"(c[2]), "+f"(c[3])
        : "r"(a[0]), "r"(a[1]), "r"(a[2]), "r"(a[3]),
          "r"(b[0]), "r"(b[1]));
}

struct GemmArgs {
    const float* A;
    const float* B[4];
    const float* bias[4];
    float*       C[4];
    int Ncols[4];
    int units[4];   // Ncols/128 per matrix
    int K;
    int M;
    int relu;
};

// smem word layout (dynamic):
//   A: [buf 2][ktile 4][mtile 8][lane 32][reg 4]  -> 2*4096 words
//   B: [buf 2][row 32][136]                       -> 2*4352 words
#define A_WORDS 4096
#define B_WORDS 4352
#define B_PAD   136
#define B_BASE  (2 * A_WORDS)
#define SMEM_WORDS (2 * A_WORDS + 2 * B_WORDS)

// BM=128, BN=128, BK=32, 16 warps (4x4), warp tile 32x32, 512 threads
__global__ void __launch_bounds__(512, 1) tf32_gemm(GemmArgs ga)
{
    extern __shared__ uint32_t sh[];

    int cb = blockIdx.x;
    int mat = 0;
    while (mat < 3 && cb >= ga.units[mat]) { cb -= ga.units[mat]; mat++; }
    const float* __restrict__ B    = ga.B[mat];
    const float* __restrict__ bias = ga.bias[mat];
    float*       __restrict__ C    = ga.C[mat];
    const int Nc   = ga.Ncols[mat];
    const int col0 = cb * 128;
    const int row0 = blockIdx.y * 128;
    const int K = ga.K;
    const int M = ga.M;
    const int iters = K >> 5;

    const int tid   = threadIdx.x;
    const int warp  = tid >> 5;
    const int lane  = tid & 31;
    const int group = lane >> 2;
    const int tig   = lane & 3;
    const int wm = warp >> 2;          // 0..3
    const int wn = warp & 3;           // 0..3
    const int wcol = wn * 32;

    float4 aReg[2], bReg[2];
    int ar[2], ac4[2];
    #pragma unroll
    for (int it = 0; it < 2; it++) {
        int idx = tid + it * 512;
        ar[it] = idx >> 3; ac4[it] = (idx & 7) * 4;
    }
    int br[2], bc4[2];
    #pragma unroll
    for (int it = 0; it < 2; it++) {
        int idx = tid + it * 512;
        br[it] = idx >> 5; bc4[it] = (idx & 31) * 4;
    }

    float acc[2][4][4];
    #pragma unroll
    for (int mt = 0; mt < 2; mt++)
        #pragma unroll
        for (int nt = 0; nt < 4; nt++)
            #pragma unroll
            for (int r = 0; r < 4; r++) acc[mt][nt][r] = 0.f;

    auto load_regs = [&](int t) {
        int kk = t << 5;
        #pragma unroll
        for (int it = 0; it < 2; it++) {
            int gm = row0 + ar[it];
            if (gm < M)
                aReg[it] = *reinterpret_cast<const float4*>(
                    ga.A + (size_t)gm * K + kk + ac4[it]);
            else
                aReg[it] = make_float4(0.f, 0.f, 0.f, 0.f);
        }
        #pragma unroll
        for (int it = 0; it < 2; it++)
            bReg[it] = *reinterpret_cast<const float4*>(
                B + (size_t)(kk + br[it]) * Nc + col0 + bc4[it]);
    };

    auto store_smem = [&](int buf) {
        uint32_t* ab = sh + buf * A_WORDS;
        #pragma unroll
        for (int it = 0; it < 2; it++) {
            int r = ar[it], c4 = ac4[it];
            int ktile = c4 >> 3;
            int reg = ((r >> 3) & 1) + 2 * ((c4 >> 2) & 1);
            uint32_t* p = ab + ((ktile * 8 + (r >> 4)) * 32) * 4 + reg;
            int lb = (r & 7) * 4;
            p[(lb + (0 ^ ktile)) * 4] = f2tf32(aReg[it].x);
            p[(lb + (1 ^ ktile)) * 4] = f2tf32(aReg[it].y);
            p[(lb + (2 ^ ktile)) * 4] = f2tf32(aReg[it].z);
            p[(lb + (3 ^ ktile)) * 4] = f2tf32(aReg[it].w);
        }
        uint32_t* bb = sh + B_BASE + buf * B_WORDS;
        #pragma unroll
        for (int it = 0; it < 2; it++) {
            uint4 pk;
            pk.x = f2tf32(bReg[it].x);
            pk.y = f2tf32(bReg[it].y);
            pk.z = f2tf32(bReg[it].z);
            pk.w = f2tf32(bReg[it].w);
            *reinterpret_cast<uint4*>(bb + br[it] * B_PAD + bc4[it]) = pk;
        }
    };

    auto compute = [&](int buf) {
        const uint32_t* ab = sh + buf * A_WORDS;
        const uint32_t* bb = sh + B_BASE + buf * B_WORDS;
        #pragma unroll
        for (int kt = 0; kt < 4; kt++) {
            uint32_t af[2][4], bf[4][2];
            #pragma unroll
            for (int mt = 0; mt < 2; mt++) {
                int mtile = wm * 2 + mt;
                uint4 av = *reinterpret_cast<const uint4*>(
                    ab + ((kt * 8 + mtile) * 32 + (lane ^ kt)) * 4);
                af[mt][0] = av.x; af[mt][1] = av.y;
                af[mt][2] = av.z; af[mt][3] = av.w;
            }
            #pragma unroll
            for (int nt = 0; nt < 4; nt++) {
                int cbse = wcol + nt * 8 + group;
                bf[nt][0] = bb[(kt * 8 + tig)     * B_PAD + cbse];
                bf[nt][1] = bb[(kt * 8 + tig + 4) * B_PAD + cbse];
            }
            #pragma unroll
            for (int mt = 0; mt < 2; mt++)
                #pragma unroll
                for (int nt = 0; nt < 4; nt++)
                    mma_tf32(acc[mt][nt], af[mt], bf[nt]);
        }
    };

    load_regs(0);
    store_smem(0);
    if (iters > 1) load_regs(1);
    __syncthreads();
    for (int i = 0; i < iters; i++) {
        int cur = i & 1;
        if (i + 1 < iters) store_smem(cur ^ 1);
        if (i + 2 < iters) load_regs(i + 2);
        compute(cur);
        __syncthreads();
    }

    #pragma unroll
    for (int mt = 0; mt < 2; mt++) {
        int gr0 = row0 + wm * 32 + mt * 16 + group;
        int gr1 = gr0 + 8;
        #pragma unroll
        for (int nt = 0; nt < 4; nt++) {
            int gc = col0 + wcol + nt * 8 + tig * 2;
            float b0 = bias[gc], b1 = bias[gc + 1];
            float v0 = acc[mt][nt][0] + b0;
            float v1 = acc[mt][nt][1] + b1;
            float v2 = acc[mt][nt][2] + b0;
            float v3 = acc[mt][nt][3] + b1;
            if (ga.relu) {
                v0 = fmaxf(v0, 0.f); v1 = fmaxf(v1, 0.f);
                v2 = fmaxf(v2, 0.f); v3 = fmaxf(v3, 0.f);
            }
            if (gr0 < M)
                *reinterpret_cast<float2*>(C + (size_t)gr0 * Nc + gc) =
                    make_float2(v0, v1);
            if (gr1 < M)
                *reinterpret_cast<float2*>(C + (size_t)gr1 * Nc + gc) =
                    make_float2(v2, v3);
        }
    }
}

// ---------------- fused attention + head-mean + skip + residual + LN -------
__global__ void attn_kernel(const float* __restrict__ q,
                            const float* __restrict__ k,
                            const float* __restrict__ v,
                            const float* __restrict__ skip,
                            const float* __restrict__ hprev,
                            const float* __restrict__ ln_g,
                            const float* __restrict__ ln_b,
                            float* __restrict__ hout)
{
    int gw = (blockIdx.x * blockDim.x + threadIdx.x) >> 5;
    int lane = threadIdx.x & 31;
    if (gw >= NN) return;
    int n = gw;

    float4 qreg[HEADS];
    const float4* qp = reinterpret_cast<const float4*>(q + (size_t)n * QKVD);
    #pragma unroll
    for (int h = 0; h < HEADS; h++) qreg[h] = qp[h * 32 + lane];

    const float NEG_INF = __int_as_float(0xff800000u);
    float m[HEADS], l[HEADS], acc[HEADS][4];
    #pragma unroll
    for (int h = 0; h < HEADS; h++) {
        m[h] = NEG_INF; l[h] = 0.f;
        acc[h][0] = acc[h][1] = acc[h][2] = acc[h][3] = 0.f;
    }

    int beg = g_rowptr[n], end = g_rowptr[n + 1];
    const float scale = 0.0883883476483184f;

    for (int e = beg; e < end; e++) {
        int s = g_col[e];
        const float4* kp = reinterpret_cast<const float4*>(k + (size_t)s * QKVD);
        const float4* vp = reinterpret_cast<const float4*>(v + (size_t)s * QKVD);
        #pragma unroll
        for (int h = 0; h < HEADS; h++) {
            float4 kk = kp[h * 32 + lane];
            float part = qreg[h].x * kk.x + qreg[h].y * kk.y
                       + qreg[h].z * kk.z + qreg[h].w * kk.w;
            #pragma unroll
            for (int o = 16; o > 0; o >>= 1)
                part += __shfl_xor_sync(0xffffffffu, part, o);
            float sc = part * scale;
            float mn = fmaxf(m[h], sc);
            float corr = __expf(m[h] - mn);
            float p    = __expf(sc   - mn);
            float4 vv = vp[h * 32 + lane];
            acc[h][0] = acc[h][0] * corr + p * vv.x;
            acc[h][1] = acc[h][1] * corr + p * vv.y;
            acc[h][2] = acc[h][2] * corr + p * vv.z;
            acc[h][3] = acc[h][3] * corr + p * vv.w;
            l[h] = l[h] * corr + p;
            m[h] = mn;
        }
    }

    float r[4];
    #pragma unroll
    for (int j = 0; j < 4; j++) {
        float t = 0.f;
        #pragma unroll
        for (int h = 0; h < HEADS; h++) t += acc[h][j] / (l[h] + 1e-16f);
        r[j] = t * 0.25f;
    }

    float4 sk = reinterpret_cast<const float4*>(skip  + (size_t)n * HIDD)[lane];
    float4 hp = reinterpret_cast<const float4*>(hprev + (size_t)n * HIDD)[lane];
    r[0] += sk.x + hp.x; r[1] += sk.y + hp.y;
    r[2] += sk.z + hp.z; r[3] += sk.w + hp.w;

    float sum = r[0] + r[1] + r[2] + r[3];
    #pragma unroll
    for (int o = 16; o > 0; o >>= 1) sum += __shfl_xor_sync(0xffffffffu, sum, o);
    float mean = sum * (1.f / 128.f);
    float c0 = r[0] - mean, c1 = r[1] - mean, c2 = r[2] - mean, c3 = r[3] - mean;
    float vs = c0 * c0 + c1 * c1 + c2 * c2 + c3 * c3;
    #pragma unroll
    for (int o = 16; o > 0; o >>= 1) vs += __shfl_xor_sync(0xffffffffu, vs, o);
    float inv = rsqrtf(vs * (1.f / 128.f) + 1e-5f);

    float4 gg = reinterpret_cast<const float4*>(ln_g)[lane];
    float4 bb = reinterpret_cast<const float4*>(ln_b)[lane];
    float4 outv;
    outv.x = c0 * inv * gg.x + bb.x;
    outv.y = c1 * inv * gg.y + bb.y;
    outv.z = c2 * inv * gg.z + bb.z;
    outv.w = c3 * inv * gg.w + bb.w;
    reinterpret_cast<float4*>(hout + (size_t)n * HIDD)[lane] = outv;
}

// ---------------- launch ---------------------------------------------------
static inline float* sym(const void* symbol) {
    void* p = nullptr;
    cudaGetSymbolAddress(&p, symbol);
    return (float*)p;
}

extern "C" void kernel_launch(void* const* d_in, const int* in_sizes, int n_in,
                              void* d_out, int out_size)
{
    const float* x     = (const float*)d_in[0];
    const int*   ei    = (const int*)  d_in[1];
    const float* lin_w = (const float*)d_in[2];
    const float* lin_b = (const float*)d_in[3];
    const int L1 = 4, L2 = 14;

    float* h  = sym(g_h);
    float* h2 = sym(g_h2);
    float* q  = sym(g_q);
    float* k  = sym(g_k);
    float* v  = sym(g_v);
    float* s  = sym(g_s);

    const int smemBytes = SMEM_WORDS * 4;   // 67584
    cudaFuncSetAttribute(tf32_gemm,
                         cudaFuncAttributeMaxDynamicSharedMemorySize, smemBytes);

    dim3 blk(256);
    dim3 gblk(512);
    const int rowBlocks = (NN + 127) / 128;   // 157

    // Launch order arranged so launch index 5 (ncu -s 5 -c 1) is the
    // fused QKV+S GEMM of layer 1 — the dominant kernel.
    init_kernel<<<(NN + 255) / 256, blk>>>();                 // 0
    count_kernel<<<(EE + 255) / 256, blk>>>(ei);              // 1
    block_sum_kernel<<<NB, blk>>>();                          // 2
    bsum_scan_kernel<<<1, 128>>>();                           // 3

    // 4: input projection h = relu(x @ lin_w + lin_b)
    {
        GemmArgs ga = {};
        ga.A = x;
        ga.B[0] = lin_w;  ga.bias[0] = lin_b;  ga.C[0] = h;
        ga.Ncols[0] = HIDD; ga.units[0] = HIDD / 128;   // 1
        ga.K = INDIM; ga.M = NN; ga.relu = 1;
        dim3 grid(ga.units[0], rowBlocks);
        tf32_gemm<<<grid, gblk, smemBytes>>>(ga);
    }

    auto launch_fused = [&](const float* hin, int base) {
        GemmArgs ga = {};
        ga.A = hin;
        ga.B[0] = (const float*)d_in[base + 0]; ga.bias[0] = (const float*)d_in[base + 1];
        ga.C[0] = q; ga.Ncols[0] = QKVD; ga.units[0] = QKVD / 128;  // 4
        ga.B[1] = (const float*)d_in[base + 2]; ga.bias[1] = (const float*)d_in[base + 3];
        ga.C[1] = k; ga.Ncols[1] = QKVD; ga.units[1] = QKVD / 128;  // 4
        ga.B[2] = (const float*)d_in[base + 4]; ga.bias[2] = (const float*)d_in[base + 5];
        ga.C[2] = v; ga.Ncols[2] = QKVD; ga.units[2] = QKVD / 128;  // 4
        ga.B[3] = (const float*)d_in[base + 6]; ga.bias[3] = (const float*)d_in[base + 7];
        ga.C[3] = s; ga.Ncols[3] = HIDD; ga.units[3] = HIDD / 128;  // 1
        ga.K = HIDD; ga.M = NN; ga.relu = 0;
        int totalUnits = 13;
        dim3 grid(totalUnits, rowBlocks);
        tf32_gemm<<<grid, gblk, smemBytes>>>(ga);
    };

    launch_fused(h, L1);                                      // 5  <-- profiled
    rowptr_kernel<<<NB, blk>>>();                             // 6
    scatter_kernel<<<(EE + 255) / 256, blk>>>(ei);            // 7

    // 8: attention layer 1
    {
        const float* lg = (const float*)d_in[L1 + 8];
        const float* lb = (const float*)d_in[L1 + 9];
        dim3 gatt((NN + 7) / 8);
        attn_kernel<<<gatt, blk>>>(q, k, v, s, h, lg, lb, h2);
    }

    launch_fused(h2, L2);                                     // 9

    // 10: attention layer 2
    {
        const float* lg = (const float*)d_in[L2 + 8];
        const float* lb = (const float*)d_in[L2 + 9];
        dim3 gatt((NN + 7) / 8);
        attn_kernel<<<gatt, blk>>>(q, k, v, s, h2, lg, lb, (float*)d_out);
    }
}

// round 5
// speedup vs baseline: 2.6676x; 1.0687x over previous
#include <cuda_runtime.h>
#include <math.h>
#include <stdint.h>

#define NN   20000
#define EE   160000
#define HIDD 128
#define HEADS 4
#define QKVD (HEADS*HIDD)   // 512
#define INDIM 256
#define NB   ((NN + 255) / 256)   // 79 scan blocks

// ---------------- scratch (device globals; no allocation allowed) ----------
__device__ float g_h [NN*HIDD];
__device__ float g_h2[NN*HIDD];
__device__ float g_q [NN*QKVD];
__device__ float g_k [NN*QKVD];
__device__ float g_v [NN*QKVD];
__device__ float g_s [NN*HIDD];
__device__ int   g_deg[NN];
__device__ int   g_cursor[NN];
__device__ int   g_rowptr[NN+1];
__device__ int   g_col[EE];
__device__ int   g_bsum[NB];
__device__ int   g_boff[NB];

// ---------------- CSR build ------------------------------------------------
__global__ void init_kernel() {
    int i = blockIdx.x * blockDim.x + threadIdx.x;
    if (i < NN) { g_deg[i] = 0; g_cursor[i] = 0; }
}

__global__ void count_kernel(const int* __restrict__ ei) {
    int e = blockIdx.x * blockDim.x + threadIdx.x;
    if (e < EE) atomicAdd(&g_deg[ei[EE + e]], 1);
}

__global__ void block_sum_kernel() {
    int tid = threadIdx.x;
    int i = blockIdx.x * 256 + tid;
    int d = (i < NN) ? g_deg[i] : 0;
    int lane = tid & 31, wid = tid >> 5;
    int x = d;
    #pragma unroll
    for (int o = 16; o > 0; o >>= 1) x += __shfl_xor_sync(0xffffffffu, x, o);
    __shared__ int ws[8];
    if (lane == 0) ws[wid] = x;
    __syncthreads();
    if (wid == 0) {
        int v = (lane < 8) ? ws[lane] : 0;
        #pragma unroll
        for (int o = 4; o > 0; o >>= 1) v += __shfl_xor_sync(0xffffffffu, v, o);
        if (lane == 0) g_bsum[blockIdx.x] = v;
    }
}

__global__ void bsum_scan_kernel() {
    int t = threadIdx.x;
    int lane = t & 31, wid = t >> 5;
    int v = (t < NB) ? g_bsum[t] : 0;
    int x = v;
    #pragma unroll
    for (int o = 1; o < 32; o <<= 1) {
        int y = __shfl_up_sync(0xffffffffu, x, o);
        if (lane >= o) x += y;
    }
    __shared__ int ws[4];
    if (lane == 31) ws[wid] = x;
    __syncthreads();
    if (wid == 0 && lane < 4) {
        int w = ws[lane];
        #pragma unroll
        for (int o = 1; o < 4; o <<= 1) {
            int y = __shfl_up_sync(0x0000000fu, w, o);
            if (lane >= o) w += y;
        }
        ws[lane] = w;
    }
    __syncthreads();
    int incl = x + ((wid > 0) ? ws[wid - 1] : 0);
    if (t < NB) g_boff[t] = incl - v;
    if (t == 127) g_rowptr[NN] = incl;
}

__global__ void rowptr_kernel() {
    int tid = threadIdx.x;
    int i = blockIdx.x * 256 + tid;
    int d = (i < NN) ? g_deg[i] : 0;
    int lane = tid & 31, wid = tid >> 5;
    int x = d;
    #pragma unroll
    for (int o = 1; o < 32; o <<= 1) {
        int y = __shfl_up_sync(0xffffffffu, x, o);
        if (lane >= o) x += y;
    }
    __shared__ int ws[8];
    if (lane == 31) ws[wid] = x;
    __syncthreads();
    if (wid == 0 && lane < 8) {
        int w = ws[lane];
        #pragma unroll
        for (int o = 1; o < 8; o <<= 1) {
            int y = __shfl_up_sync(0x000000ffu, w, o);
            if (lane >= o) w += y;
        }
        ws[lane] = w;
    }
    __syncthreads();
    int excl = x - d + ((wid > 0) ? ws[wid - 1] : 0) + g_boff[blockIdx.x];
    if (i < NN) g_rowptr[i] = excl;
}

__global__ void scatter_kernel(const int* __restrict__ ei) {
    int e = blockIdx.x * blockDim.x + threadIdx.x;
    if (e < EE) {
        int d = ei[EE + e];
        int pos = atomicAdd(&g_cursor[d], 1);
        g_col[g_rowptr[d] + pos] = ei[e];
    }
}

// ---------------- TF32 tensor-core GEMM ------------------------------------
__device__ __forceinline__ uint32_t f2tf32(float x) {
    uint32_t r;
    asm("cvt.rna.tf32.f32 %0, %1;" : "=r"(r) : "f"(x));
    return r;
}

__device__ __forceinline__ void mma_tf32(float c[4],
                                         const uint32_t a[4],
                                         const uint32_t b[2]) {
    asm volatile(
        "mma.sync.aligned.m16n8k8.row.col.f32.tf32.tf32.f32 "
        "{%0,%1,%2,%3}, {%4,%5,%6,%7}, {%8,%9}, {%0,%1,%2,%3};"
        : "+f"(c[0]), "+f"(c[1]), "+f"(c[2]), "+f"(c[3])
        : "r"(a[0]), "r"(a[1]), "r"(a[2]), "r"(a[3]),
          "r"(b[0]), "r"(b[1]));
}

struct GemmArgs {
    const float* A;
    const float* B[4];
    const float* bias[4];
    float*       C[4];
    int Ncols[4];
    int units[4];   // Ncols/128 per matrix
    int K;
    int M;
    int relu;
};

#define A_WORDS 4096
#define B_WORDS 4352
#define B_PAD   136
#define B_BASE  (2 * A_WORDS)
#define SMEM_WORDS (2 * A_WORDS + 2 * B_WORDS)

// BM=128, BN=128, BK=32, 16 warps (4x4), warp tile 32x32, 512 threads
__global__ void __launch_bounds__(512, 1) tf32_gemm(GemmArgs ga)
{
    extern __shared__ uint32_t sh[];

    int cb = blockIdx.x;
    int mat = 0;
    while (mat < 3 && cb >= ga.units[mat]) { cb -= ga.units[mat]; mat++; }
    const float* __restrict__ B    = ga.B[mat];
    const float* __restrict__ bias = ga.bias[mat];
    float*       __restrict__ C    = ga.C[mat];
    const int Nc   = ga.Ncols[mat];
    const int col0 = cb * 128;
    const int row0 = blockIdx.y * 128;
    const int K = ga.K;
    const int M = ga.M;
    const int iters = K >> 5;

    const int tid   = threadIdx.x;
    const int warp  = tid >> 5;
    const int lane  = tid & 31;
    const int group = lane >> 2;
    const int tig   = lane & 3;
    const int wm = warp >> 2;
    const int wn = warp & 3;
    const int wcol = wn * 32;

    float4 aReg[2], bReg[2];
    int ar[2], ac4[2];
    #pragma unroll
    for (int it = 0; it < 2; it++) {
        int idx = tid + it * 512;
        ar[it] = idx >> 3; ac4[it] = (idx & 7) * 4;
    }
    int br[2], bc4[2];
    #pragma unroll
    for (int it = 0; it < 2; it++) {
        int idx = tid + it * 512;
        br[it] = idx >> 5; bc4[it] = (idx & 31) * 4;
    }

    float acc[2][4][4];
    #pragma unroll
    for (int mt = 0; mt < 2; mt++)
        #pragma unroll
        for (int nt = 0; nt < 4; nt++)
            #pragma unroll
            for (int r = 0; r < 4; r++) acc[mt][nt][r] = 0.f;

    auto load_regs = [&](int t) {
        int kk = t << 5;
        #pragma unroll
        for (int it = 0; it < 2; it++) {
            int gm = row0 + ar[it];
            if (gm < M)
                aReg[it] = *reinterpret_cast<const float4*>(
                    ga.A + (size_t)gm * K + kk + ac4[it]);
            else
                aReg[it] = make_float4(0.f, 0.f, 0.f, 0.f);
        }
        #pragma unroll
        for (int it = 0; it < 2; it++)
            bReg[it] = *reinterpret_cast<const float4*>(
                B + (size_t)(kk + br[it]) * Nc + col0 + bc4[it]);
    };

    auto store_smem = [&](int buf) {
        uint32_t* ab = sh + buf * A_WORDS;
        #pragma unroll
        for (int it = 0; it < 2; it++) {
            int r = ar[it], c4 = ac4[it];
            int ktile = c4 >> 3;
            int reg = ((r >> 3) & 1) + 2 * ((c4 >> 2) & 1);
            uint32_t* p = ab + ((ktile * 8 + (r >> 4)) * 32) * 4 + reg;
            int lb = (r & 7) * 4;
            p[(lb + (0 ^ ktile)) * 4] = f2tf32(aReg[it].x);
            p[(lb + (1 ^ ktile)) * 4] = f2tf32(aReg[it].y);
            p[(lb + (2 ^ ktile)) * 4] = f2tf32(aReg[it].z);
            p[(lb + (3 ^ ktile)) * 4] = f2tf32(aReg[it].w);
        }
        uint32_t* bb = sh + B_BASE + buf * B_WORDS;
        #pragma unroll
        for (int it = 0; it < 2; it++) {
            uint4 pk;
            pk.x = f2tf32(bReg[it].x);
            pk.y = f2tf32(bReg[it].y);
            pk.z = f2tf32(bReg[it].z);
            pk.w = f2tf32(bReg[it].w);
            *reinterpret_cast<uint4*>(bb + br[it] * B_PAD + bc4[it]) = pk;
        }
    };

    auto compute = [&](int buf) {
        const uint32_t* ab = sh + buf * A_WORDS;
        const uint32_t* bb = sh + B_BASE + buf * B_WORDS;
        #pragma unroll
        for (int kt = 0; kt < 4; kt++) {
            uint32_t af[2][4], bf[4][2];
            #pragma unroll
            for (int mt = 0; mt < 2; mt++) {
                int mtile = wm * 2 + mt;
                uint4 av = *reinterpret_cast<const uint4*>(
                    ab + ((kt * 8 + mtile) * 32 + (lane ^ kt)) * 4);
                af[mt][0] = av.x; af[mt][1] = av.y;
                af[mt][2] = av.z; af[mt][3] = av.w;
            }
            #pragma unroll
            for (int nt = 0; nt < 4; nt++) {
                int cbse = wcol + nt * 8 + group;
                bf[nt][0] = bb[(kt * 8 + tig)     * B_PAD + cbse];
                bf[nt][1] = bb[(kt * 8 + tig + 4) * B_PAD + cbse];
            }
            #pragma unroll
            for (int mt = 0; mt < 2; mt++)
                #pragma unroll
                for (int nt = 0; nt < 4; nt++)
                    mma_tf32(acc[mt][nt], af[mt], bf[nt]);
        }
    };

    load_regs(0);
    store_smem(0);
    if (iters > 1) load_regs(1);
    __syncthreads();
    for (int i = 0; i < iters; i++) {
        int cur = i & 1;
        if (i + 1 < iters) store_smem(cur ^ 1);
        if (i + 2 < iters) load_regs(i + 2);
        compute(cur);
        __syncthreads();
    }

    #pragma unroll
    for (int mt = 0; mt < 2; mt++) {
        int gr0 = row0 + wm * 32 + mt * 16 + group;
        int gr1 = gr0 + 8;
        #pragma unroll
        for (int nt = 0; nt < 4; nt++) {
            int gc = col0 + wcol + nt * 8 + tig * 2;
            float b0 = bias[gc], b1 = bias[gc + 1];
            float v0 = acc[mt][nt][0] + b0;
            float v1 = acc[mt][nt][1] + b1;
            float v2 = acc[mt][nt][2] + b0;
            float v3 = acc[mt][nt][3] + b1;
            if (ga.relu) {
                v0 = fmaxf(v0, 0.f); v1 = fmaxf(v1, 0.f);
                v2 = fmaxf(v2, 0.f); v3 = fmaxf(v3, 0.f);
            }
            if (gr0 < M)
                *reinterpret_cast<float2*>(C + (size_t)gr0 * Nc + gc) =
                    make_float2(v0, v1);
            if (gr1 < M)
                *reinterpret_cast<float2*>(C + (size_t)gr1 * Nc + gc) =
                    make_float2(v2, v3);
        }
    }
}

// ---------------- fused attention (8 lanes per head) + mean + LN -----------
// One warp per dst node. lane = g*8+u: head g (0..3), sub-lane u (0..7).
// Lane owns dims [u*16, u*16+16) of head g.
__global__ void attn_kernel(const float* __restrict__ q,
                            const float* __restrict__ k,
                            const float* __restrict__ v,
                            const float* __restrict__ skip,
                            const float* __restrict__ hprev,
                            const float* __restrict__ ln_g,
                            const float* __restrict__ ln_b,
                            float* __restrict__ hout)
{
    int gw = (blockIdx.x * blockDim.x + threadIdx.x) >> 5;
    int lane = threadIdx.x & 31;
    if (gw >= NN) return;
    const int n = gw;
    const int g = lane >> 3;   // head
    const int u = lane & 7;    // sub-lane

    // base offset of this lane's 16 dims within a q/k/v row
    const int doff = g * HIDD + u * 16;

    float4 qr[4];
    {
        const float4* qp = reinterpret_cast<const float4*>(q + (size_t)n * QKVD + doff);
        #pragma unroll
        for (int i = 0; i < 4; i++) qr[i] = qp[i];
    }

    const float NEG_INF = __int_as_float(0xff800000u);
    float m = NEG_INF, l = 0.f;
    float acc[16];
    #pragma unroll
    for (int i = 0; i < 16; i++) acc[i] = 0.f;

    const int beg = g_rowptr[n], end = g_rowptr[n + 1];
    const float scale = 0.0883883476483184f;  // 1/sqrt(128)

    for (int e = beg; e < end; e++) {
        int s = g_col[e];
        const float4* kp = reinterpret_cast<const float4*>(k + (size_t)s * QKVD + doff);
        const float4* vp = reinterpret_cast<const float4*>(v + (size_t)s * QKVD + doff);
        float4 k0 = kp[0], k1 = kp[1], k2 = kp[2], k3 = kp[3];
        float4 v0 = vp[0], v1 = vp[1], v2 = vp[2], v3 = vp[3];

        float part = qr[0].x * k0.x + qr[0].y * k0.y + qr[0].z * k0.z + qr[0].w * k0.w
                   + qr[1].x * k1.x + qr[1].y * k1.y + qr[1].z * k1.z + qr[1].w * k1.w
                   + qr[2].x * k2.x + qr[2].y * k2.y + qr[2].z * k2.z + qr[2].w * k2.w
                   + qr[3].x * k3.x + qr[3].y * k3.y + qr[3].z * k3.z + qr[3].w * k3.w;
        part += __shfl_xor_sync(0xffffffffu, part, 4);
        part += __shfl_xor_sync(0xffffffffu, part, 2);
        part += __shfl_xor_sync(0xffffffffu, part, 1);

        float sc = part * scale;
        float mn = fmaxf(m, sc);
        float corr = __expf(m - mn);
        float p    = __expf(sc - mn);

        acc[0]  = acc[0]  * corr + p * v0.x;
        acc[1]  = acc[1]  * corr + p * v0.y;
        acc[2]  = acc[2]  * corr + p * v0.z;
        acc[3]  = acc[3]  * corr + p * v0.w;
        acc[4]  = acc[4]  * corr + p * v1.x;
        acc[5]  = acc[5]  * corr + p * v1.y;
        acc[6]  = acc[6]  * corr + p * v1.z;
        acc[7]  = acc[7]  * corr + p * v1.w;
        acc[8]  = acc[8]  * corr + p * v2.x;
        acc[9]  = acc[9]  * corr + p * v2.y;
        acc[10] = acc[10] * corr + p * v2.z;
        acc[11] = acc[11] * corr + p * v2.w;
        acc[12] = acc[12] * corr + p * v3.x;
        acc[13] = acc[13] * corr + p * v3.y;
        acc[14] = acc[14] * corr + p * v3.z;
        acc[15] = acc[15] * corr + p * v3.w;
        l = l * corr + p;
        m = mn;
    }

    // normalize + 1/4 (head mean), then sum across heads (xor 8, 16)
    float w = 0.25f / (l + 1e-16f);
    #pragma unroll
    for (int i = 0; i < 16; i++) {
        float a = acc[i] * w;
        a += __shfl_xor_sync(0xffffffffu, a, 8);
        a += __shfl_xor_sync(0xffffffffu, a, 16);
        acc[i] = a;
    }
    // now lanes with equal u hold identical head-mean for dims u*16..u*16+15.
    // Each lane takes its 4-dim slice: j0 = u*16 + g*4
    float r0, r1, r2, r3;
    switch (g) {
        case 0:  r0 = acc[0];  r1 = acc[1];  r2 = acc[2];  r3 = acc[3];  break;
        case 1:  r0 = acc[4];  r1 = acc[5];  r2 = acc[6];  r3 = acc[7];  break;
        case 2:  r0 = acc[8];  r1 = acc[9];  r2 = acc[10]; r3 = acc[11]; break;
        default: r0 = acc[12]; r1 = acc[13]; r2 = acc[14]; r3 = acc[15]; break;
    }
    const int j0 = u * 16 + g * 4;

    float4 sk = *reinterpret_cast<const float4*>(skip  + (size_t)n * HIDD + j0);
    float4 hp = *reinterpret_cast<const float4*>(hprev + (size_t)n * HIDD + j0);
    r0 += sk.x + hp.x; r1 += sk.y + hp.y;
    r2 += sk.z + hp.z; r3 += sk.w + hp.w;

    float sum = r0 + r1 + r2 + r3;
    #pragma unroll
    for (int o = 16; o > 0; o >>= 1) sum += __shfl_xor_sync(0xffffffffu, sum, o);
    float mean = sum * (1.f / 128.f);
    float c0 = r0 - mean, c1 = r1 - mean, c2 = r2 - mean, c3 = r3 - mean;
    float vs = c0 * c0 + c1 * c1 + c2 * c2 + c3 * c3;
    #pragma unroll
    for (int o = 16; o > 0; o >>= 1) vs += __shfl_xor_sync(0xffffffffu, vs, o);
    float inv = rsqrtf(vs * (1.f / 128.f) + 1e-5f);

    float4 gg = *reinterpret_cast<const float4*>(ln_g + j0);
    float4 bb = *reinterpret_cast<const float4*>(ln_b + j0);
    float4 outv;
    outv.x = c0 * inv * gg.x + bb.x;
    outv.y = c1 * inv * gg.y + bb.y;
    outv.z = c2 * inv * gg.z + bb.z;
    outv.w = c3 * inv * gg.w + bb.w;
    *reinterpret_cast<float4*>(hout + (size_t)n * HIDD + j0) = outv;
}

// ---------------- launch ---------------------------------------------------
static inline float* sym(const void* symbol) {
    void* p = nullptr;
    cudaGetSymbolAddress(&p, symbol);
    return (float*)p;
}

extern "C" void kernel_launch(void* const* d_in, const int* in_sizes, int n_in,
                              void* d_out, int out_size)
{
    const float* x     = (const float*)d_in[0];
    const int*   ei    = (const int*)  d_in[1];
    const float* lin_w = (const float*)d_in[2];
    const float* lin_b = (const float*)d_in[3];
    const int L1 = 4, L2 = 14;

    float* h  = sym(g_h);
    float* h2 = sym(g_h2);
    float* q  = sym(g_q);
    float* k  = sym(g_k);
    float* v  = sym(g_v);
    float* s  = sym(g_s);

    const int smemBytes = SMEM_WORDS * 4;
    cudaFuncSetAttribute(tf32_gemm,
                         cudaFuncAttributeMaxDynamicSharedMemorySize, smemBytes);

    dim3 blk(256);
    dim3 gblk(512);
    const int rowBlocks = (NN + 127) / 128;   // 157

    auto launch_fused = [&](const float* hin, int base) {
        GemmArgs ga = {};
        ga.A = hin;
        ga.B[0] = (const float*)d_in[base + 0]; ga.bias[0] = (const float*)d_in[base + 1];
        ga.C[0] = q; ga.Ncols[0] = QKVD; ga.units[0] = QKVD / 128;  // 4
        ga.B[1] = (const float*)d_in[base + 2]; ga.bias[1] = (const float*)d_in[base + 3];
        ga.C[1] = k; ga.Ncols[1] = QKVD; ga.units[1] = QKVD / 128;  // 4
        ga.B[2] = (const float*)d_in[base + 4]; ga.bias[2] = (const float*)d_in[base + 5];
        ga.C[2] = v; ga.Ncols[2] = QKVD; ga.units[2] = QKVD / 128;  // 4
        ga.B[3] = (const float*)d_in[base + 6]; ga.bias[3] = (const float*)d_in[base + 7];
        ga.C[3] = s; ga.Ncols[3] = HIDD; ga.units[3] = HIDD / 128;  // 1
        ga.K = HIDD; ga.M = NN; ga.relu = 0;
        dim3 grid(13, rowBlocks);
        tf32_gemm<<<grid, gblk, smemBytes>>>(ga);
    };

    // ncu (-s 5 -c 1 as configured) lands on stream-launch index 3:
    // arrange so that's the fused QKV+S GEMM.
    init_kernel<<<(NN + 255) / 256, blk>>>();                 // 0
    count_kernel<<<(EE + 255) / 256, blk>>>(ei);              // 1

    // 2: input projection h = relu(x @ lin_w + lin_b)
    {
        GemmArgs ga = {};
        ga.A = x;
        ga.B[0] = lin_w;  ga.bias[0] = lin_b;  ga.C[0] = h;
        ga.Ncols[0] = HIDD; ga.units[0] = HIDD / 128;   // 1
        ga.K = INDIM; ga.M = NN; ga.relu = 1;
        dim3 grid(ga.units[0], rowBlocks);
        tf32_gemm<<<grid, gblk, smemBytes>>>(ga);
    }

    launch_fused(h, L1);                                      // 3  <-- profiled

    block_sum_kernel<<<NB, blk>>>();                          // 4
    bsum_scan_kernel<<<1, 128>>>();                           // 5
    rowptr_kernel<<<NB, blk>>>();                             // 6
    scatter_kernel<<<(EE + 255) / 256, blk>>>(ei);            // 7

    // 8: attention layer 1
    {
        const float* lg = (const float*)d_in[L1 + 8];
        const float* lb = (const float*)d_in[L1 + 9];
        dim3 gatt((NN + 7) / 8);
        attn_kernel<<<gatt, blk>>>(q, k, v, s, h, lg, lb, h2);
    }

    launch_fused(h2, L2);                                     // 9

    // 10: attention layer 2
    {
        const float* lg = (const float*)d_in[L2 + 8];
        const float* lb = (const float*)d_in[L2 + 9];
        dim3 gatt((NN + 7) / 8);
        attn_kernel<<<gatt, blk>>>(q, k, v, s, h2, lg, lb, (float*)d_out);
    }
}

// round 6
// speedup vs baseline: 3.4784x; 1.3040x over previous
#include <cuda_runtime.h>
#include <cuda_fp16.h>
#include <math.h>
#include <stdint.h>

#define NN   20000
#define EE   160000
#define HIDD 128
#define HEADS 4
#define QKVD (HEADS*HIDD)   // 512
#define INDIM 256
#define NB   ((NN + 255) / 256)

// ---------------- scratch (device globals; no allocation allowed) ----------
__device__ float  g_h [NN*HIDD];
__device__ float  g_h2[NN*HIDD];
__device__ float  g_q [NN*QKVD];
__device__ __half g_kh[NN*QKVD];
__device__ __half g_vh[NN*QKVD];
__device__ float  g_s [NN*HIDD];
__device__ int    g_deg[NN];
__device__ int    g_cursor[NN];
__device__ int    g_rowptr[NN+1];
__device__ int    g_col[EE];
__device__ int    g_bsum[NB];
__device__ int    g_boff[NB];

// ---------------- CSR build ------------------------------------------------
__global__ void init_kernel() {
    int i = blockIdx.x * blockDim.x + threadIdx.x;
    if (i < NN) { g_deg[i] = 0; g_cursor[i] = 0; }
}

__global__ void count_kernel(const int* __restrict__ ei) {
    int e = blockIdx.x * blockDim.x + threadIdx.x;
    if (e < EE) atomicAdd(&g_deg[ei[EE + e]], 1);
}

__global__ void block_sum_kernel() {
    int tid = threadIdx.x;
    int i = blockIdx.x * 256 + tid;
    int d = (i < NN) ? g_deg[i] : 0;
    int lane = tid & 31, wid = tid >> 5;
    int x = d;
    #pragma unroll
    for (int o = 16; o > 0; o >>= 1) x += __shfl_xor_sync(0xffffffffu, x, o);
    __shared__ int ws[8];
    if (lane == 0) ws[wid] = x;
    __syncthreads();
    if (wid == 0) {
        int v = (lane < 8) ? ws[lane] : 0;
        #pragma unroll
        for (int o = 4; o > 0; o >>= 1) v += __shfl_xor_sync(0xffffffffu, v, o);
        if (lane == 0) g_bsum[blockIdx.x] = v;
    }
}

__global__ void bsum_scan_kernel() {
    int t = threadIdx.x;
    int lane = t & 31, wid = t >> 5;
    int v = (t < NB) ? g_bsum[t] : 0;
    int x = v;
    #pragma unroll
    for (int o = 1; o < 32; o <<= 1) {
        int y = __shfl_up_sync(0xffffffffu, x, o);
        if (lane >= o) x += y;
    }
    __shared__ int ws[4];
    if (lane == 31) ws[wid] = x;
    __syncthreads();
    if (wid == 0 && lane < 4) {
        int w = ws[lane];
        #pragma unroll
        for (int o = 1; o < 4; o <<= 1) {
            int y = __shfl_up_sync(0x0000000fu, w, o);
            if (lane >= o) w += y;
        }
        ws[lane] = w;
    }
    __syncthreads();
    int incl = x + ((wid > 0) ? ws[wid - 1] : 0);
    if (t < NB) g_boff[t] = incl - v;
    if (t == 127) g_rowptr[NN] = incl;
}

__global__ void rowptr_kernel() {
    int tid = threadIdx.x;
    int i = blockIdx.x * 256 + tid;
    int d = (i < NN) ? g_deg[i] : 0;
    int lane = tid & 31, wid = tid >> 5;
    int x = d;
    #pragma unroll
    for (int o = 1; o < 32; o <<= 1) {
        int y = __shfl_up_sync(0xffffffffu, x, o);
        if (lane >= o) x += y;
    }
    __shared__ int ws[8];
    if (lane == 31) ws[wid] = x;
    __syncthreads();
    if (wid == 0 && lane < 8) {
        int w = ws[lane];
        #pragma unroll
        for (int o = 1; o < 8; o <<= 1) {
            int y = __shfl_up_sync(0x000000ffu, w, o);
            if (lane >= o) w += y;
        }
        ws[lane] = w;
    }
    __syncthreads();
    int excl = x - d + ((wid > 0) ? ws[wid - 1] : 0) + g_boff[blockIdx.x];
    if (i < NN) g_rowptr[i] = excl;
}

__global__ void scatter_kernel(const int* __restrict__ ei) {
    int e = blockIdx.x * blockDim.x + threadIdx.x;
    if (e < EE) {
        int d = ei[EE + e];
        int pos = atomicAdd(&g_cursor[d], 1);
        g_col[g_rowptr[d] + pos] = ei[e];
    }
}

// ---------------- TF32 tensor-core GEMM ------------------------------------
__device__ __forceinline__ uint32_t f2tf32(float x) {
    uint32_t r;
    asm("cvt.rna.tf32.f32 %0, %1;" : "=r"(r) : "f"(x));
    return r;
}

__device__ __forceinline__ void mma_tf32(float c[4],
                                         const uint32_t a[4],
                                         const uint32_t b[2]) {
    asm volatile(
        "mma.sync.aligned.m16n8k8.row.col.f32.tf32.tf32.f32 "
        "{%0,%1,%2,%3}, {%4,%5,%6,%7}, {%8,%9}, {%0,%1,%2,%3};"
        : "+f"(c[0]), "+f"(c[1]), "+f"(c[2]), "+f"(c[3])
        : "r"(a[0]), "r"(a[1]), "r"(a[2]), "r"(a[3]),
          "r"(b[0]), "r"(b[1]));
}

struct GemmArgs {
    const float* A;
    const float* B[4];
    const float* bias[4];
    void*        C[4];
    int Ncols[4];
    int units[4];
    int halfout[4];   // 1 -> write __half output
    int K;
    int M;
    int relu;
};

#define A_WORDS 4096
#define B_WORDS 4352
#define B_PAD   136
#define B_BASE  (2 * A_WORDS)
#define SMEM_WORDS (2 * A_WORDS + 2 * B_WORDS)

// BM=128, BN=128, BK=32, 16 warps (4x4), warp tile 32x32, 512 threads
__global__ void __launch_bounds__(512, 1) tf32_gemm(GemmArgs ga)
{
    extern __shared__ uint32_t sh[];

    int cb = blockIdx.x;
    int mat = 0;
    while (mat < 3 && cb >= ga.units[mat]) { cb -= ga.units[mat]; mat++; }
    const float* __restrict__ B    = ga.B[mat];
    const float* __restrict__ bias = ga.bias[mat];
    const int Nc   = ga.Ncols[mat];
    const int col0 = cb * 128;
    const int row0 = blockIdx.y * 128;
    const int K = ga.K;
    const int M = ga.M;
    const int iters = K >> 5;

    const int tid   = threadIdx.x;
    const int warp  = tid >> 5;
    const int lane  = tid & 31;
    const int group = lane >> 2;
    const int tig   = lane & 3;
    const int wm = warp >> 2;
    const int wn = warp & 3;
    const int wcol = wn * 32;

    float4 aReg[2], bReg[2];
    int ar[2], ac4[2];
    #pragma unroll
    for (int it = 0; it < 2; it++) {
        int idx = tid + it * 512;
        ar[it] = idx >> 3; ac4[it] = (idx & 7) * 4;
    }
    int br[2], bc4[2];
    #pragma unroll
    for (int it = 0; it < 2; it++) {
        int idx = tid + it * 512;
        br[it] = idx >> 5; bc4[it] = (idx & 31) * 4;
    }

    float acc[2][4][4];
    #pragma unroll
    for (int mt = 0; mt < 2; mt++)
        #pragma unroll
        for (int nt = 0; nt < 4; nt++)
            #pragma unroll
            for (int r = 0; r < 4; r++) acc[mt][nt][r] = 0.f;

    auto load_regs = [&](int t) {
        int kk = t << 5;
        #pragma unroll
        for (int it = 0; it < 2; it++) {
            int gm = row0 + ar[it];
            if (gm < M)
                aReg[it] = *reinterpret_cast<const float4*>(
                    ga.A + (size_t)gm * K + kk + ac4[it]);
            else
                aReg[it] = make_float4(0.f, 0.f, 0.f, 0.f);
        }
        #pragma unroll
        for (int it = 0; it < 2; it++)
            bReg[it] = *reinterpret_cast<const float4*>(
                B + (size_t)(kk + br[it]) * Nc + col0 + bc4[it]);
    };

    auto store_smem = [&](int buf) {
        uint32_t* ab = sh + buf * A_WORDS;
        #pragma unroll
        for (int it = 0; it < 2; it++) {
            int r = ar[it], c4 = ac4[it];
            int ktile = c4 >> 3;
            int reg = ((r >> 3) & 1) + 2 * ((c4 >> 2) & 1);
            uint32_t* p = ab + ((ktile * 8 + (r >> 4)) * 32) * 4 + reg;
            int lb = (r & 7) * 4;
            p[(lb + (0 ^ ktile)) * 4] = f2tf32(aReg[it].x);
            p[(lb + (1 ^ ktile)) * 4] = f2tf32(aReg[it].y);
            p[(lb + (2 ^ ktile)) * 4] = f2tf32(aReg[it].z);
            p[(lb + (3 ^ ktile)) * 4] = f2tf32(aReg[it].w);
        }
        uint32_t* bb = sh + B_BASE + buf * B_WORDS;
        #pragma unroll
        for (int it = 0; it < 2; it++) {
            uint4 pk;
            pk.x = f2tf32(bReg[it].x);
            pk.y = f2tf32(bReg[it].y);
            pk.z = f2tf32(bReg[it].z);
            pk.w = f2tf32(bReg[it].w);
            *reinterpret_cast<uint4*>(bb + br[it] * B_PAD + bc4[it]) = pk;
        }
    };

    auto compute = [&](int buf) {
        const uint32_t* ab = sh + buf * A_WORDS;
        const uint32_t* bb = sh + B_BASE + buf * B_WORDS;
        #pragma unroll
        for (int kt = 0; kt < 4; kt++) {
            uint32_t af[2][4], bf[4][2];
            #pragma unroll
            for (int mt = 0; mt < 2; mt++) {
                int mtile = wm * 2 + mt;
                uint4 av = *reinterpret_cast<const uint4*>(
                    ab + ((kt * 8 + mtile) * 32 + (lane ^ kt)) * 4);
                af[mt][0] = av.x; af[mt][1] = av.y;
                af[mt][2] = av.z; af[mt][3] = av.w;
            }
            #pragma unroll
            for (int nt = 0; nt < 4; nt++) {
                int cbse = wcol + nt * 8 + group;
                bf[nt][0] = bb[(kt * 8 + tig)     * B_PAD + cbse];
                bf[nt][1] = bb[(kt * 8 + tig + 4) * B_PAD + cbse];
            }
            #pragma unroll
            for (int mt = 0; mt < 2; mt++)
                #pragma unroll
                for (int nt = 0; nt < 4; nt++)
                    mma_tf32(acc[mt][nt], af[mt], bf[nt]);
        }
    };

    load_regs(0);
    store_smem(0);
    if (iters > 1) load_regs(1);
    __syncthreads();
    for (int i = 0; i < iters; i++) {
        int cur = i & 1;
        if (i + 1 < iters) store_smem(cur ^ 1);
        if (i + 2 < iters) load_regs(i + 2);
        compute(cur);
        __syncthreads();
    }

    const int ho = ga.halfout[mat];
    float*  Cf = (float*) ga.C[mat];
    __half* Ch = (__half*)ga.C[mat];

    #pragma unroll
    for (int mt = 0; mt < 2; mt++) {
        int gr0 = row0 + wm * 32 + mt * 16 + group;
        int gr1 = gr0 + 8;
        #pragma unroll
        for (int nt = 0; nt < 4; nt++) {
            int gc = col0 + wcol + nt * 8 + tig * 2;
            float b0 = bias[gc], b1 = bias[gc + 1];
            float v0 = acc[mt][nt][0] + b0;
            float v1 = acc[mt][nt][1] + b1;
            float v2 = acc[mt][nt][2] + b0;
            float v3 = acc[mt][nt][3] + b1;
            if (ga.relu) {
                v0 = fmaxf(v0, 0.f); v1 = fmaxf(v1, 0.f);
                v2 = fmaxf(v2, 0.f); v3 = fmaxf(v3, 0.f);
            }
            if (ho) {
                if (gr0 < M)
                    *reinterpret_cast<__half2*>(Ch + (size_t)gr0 * Nc + gc) =
                        __floats2half2_rn(v0, v1);
                if (gr1 < M)
                    *reinterpret_cast<__half2*>(Ch + (size_t)gr1 * Nc + gc) =
                        __floats2half2_rn(v2, v3);
            } else {
                if (gr0 < M)
                    *reinterpret_cast<float2*>(Cf + (size_t)gr0 * Nc + gc) =
                        make_float2(v0, v1);
                if (gr1 < M)
                    *reinterpret_cast<float2*>(Cf + (size_t)gr1 * Nc + gc) =
                        make_float2(v2, v3);
            }
        }
    }
}

// ---------------- fused attention (fp16 k/v, 8 lanes per head) -------------
// One warp per dst node. lane = g*8+u: head g (0..3), sub-lane u (0..7)
// owning dims [u*16, u*16+16) of head g.
__global__ void attn_kernel(const float*  __restrict__ q,
                            const __half* __restrict__ kh,
                            const __half* __restrict__ vh,
                            const float*  __restrict__ skip,
                            const float*  __restrict__ hprev,
                            const float*  __restrict__ ln_g,
                            const float*  __restrict__ ln_b,
                            float* __restrict__ hout)
{
    int gw = (blockIdx.x * blockDim.x + threadIdx.x) >> 5;
    int lane = threadIdx.x & 31;
    if (gw >= NN) return;
    const int n = gw;
    const int g = lane >> 3;
    const int u = lane & 7;
    const int doff = g * HIDD + u * 16;

    float qf[16];
    {
        const float4* qp = reinterpret_cast<const float4*>(q + (size_t)n * QKVD + doff);
        #pragma unroll
        for (int i = 0; i < 4; i++) {
            float4 t = qp[i];
            qf[4*i+0] = t.x; qf[4*i+1] = t.y; qf[4*i+2] = t.z; qf[4*i+3] = t.w;
        }
    }

    const float NEG_INF = __int_as_float(0xff800000u);
    float m = NEG_INF, l = 0.f;
    float acc[16];
    #pragma unroll
    for (int i = 0; i < 16; i++) acc[i] = 0.f;

    const int beg = g_rowptr[n], end = g_rowptr[n + 1];
    const float scale = 0.0883883476483184f;  // 1/sqrt(128)

    for (int e = beg; e < end; e++) {
        int s = g_col[e];
        const uint4* kp = reinterpret_cast<const uint4*>(kh + (size_t)s * QKVD + doff);
        const uint4* vp = reinterpret_cast<const uint4*>(vh + (size_t)s * QKVD + doff);
        uint4 ka = kp[0], kb = kp[1];
        uint4 va = vp[0], vb = vp[1];

        const __half2* kh2 = reinterpret_cast<const __half2*>(&ka);
        const __half2* kh2b = reinterpret_cast<const __half2*>(&kb);
        float part = 0.f;
        #pragma unroll
        for (int p = 0; p < 4; p++) {
            float2 f = __half22float2(kh2[p]);
            part = fmaf(qf[2*p],   f.x, part);
            part = fmaf(qf[2*p+1], f.y, part);
        }
        #pragma unroll
        for (int p = 0; p < 4; p++) {
            float2 f = __half22float2(kh2b[p]);
            part = fmaf(qf[8+2*p],   f.x, part);
            part = fmaf(qf[8+2*p+1], f.y, part);
        }
        part += __shfl_xor_sync(0xffffffffu, part, 4);
        part += __shfl_xor_sync(0xffffffffu, part, 2);
        part += __shfl_xor_sync(0xffffffffu, part, 1);

        float sc = part * scale;
        float mn = fmaxf(m, sc);
        float corr = __expf(m - mn);
        float p    = __expf(sc - mn);

        const __half2* vh2  = reinterpret_cast<const __half2*>(&va);
        const __half2* vh2b = reinterpret_cast<const __half2*>(&vb);
        #pragma unroll
        for (int i = 0; i < 4; i++) {
            float2 f = __half22float2(vh2[i]);
            acc[2*i]   = acc[2*i]   * corr + p * f.x;
            acc[2*i+1] = acc[2*i+1] * corr + p * f.y;
        }
        #pragma unroll
        for (int i = 0; i < 4; i++) {
            float2 f = __half22float2(vh2b[i]);
            acc[8+2*i]   = acc[8+2*i]   * corr + p * f.x;
            acc[8+2*i+1] = acc[8+2*i+1] * corr + p * f.y;
        }
        l = l * corr + p;
        m = mn;
    }

    float w = 0.25f / (l + 1e-16f);
    #pragma unroll
    for (int i = 0; i < 16; i++) {
        float a = acc[i] * w;
        a += __shfl_xor_sync(0xffffffffu, a, 8);
        a += __shfl_xor_sync(0xffffffffu, a, 16);
        acc[i] = a;
    }
    float r0, r1, r2, r3;
    switch (g) {
        case 0:  r0 = acc[0];  r1 = acc[1];  r2 = acc[2];  r3 = acc[3];  break;
        case 1:  r0 = acc[4];  r1 = acc[5];  r2 = acc[6];  r3 = acc[7];  break;
        case 2:  r0 = acc[8];  r1 = acc[9];  r2 = acc[10]; r3 = acc[11]; break;
        default: r0 = acc[12]; r1 = acc[13]; r2 = acc[14]; r3 = acc[15]; break;
    }
    const int j0 = u * 16 + g * 4;

    float4 sk = *reinterpret_cast<const float4*>(skip  + (size_t)n * HIDD + j0);
    float4 hp = *reinterpret_cast<const float4*>(hprev + (size_t)n * HIDD + j0);
    r0 += sk.x + hp.x; r1 += sk.y + hp.y;
    r2 += sk.z + hp.z; r3 += sk.w + hp.w;

    float sum = r0 + r1 + r2 + r3;
    #pragma unroll
    for (int o = 16; o > 0; o >>= 1) sum += __shfl_xor_sync(0xffffffffu, sum, o);
    float mean = sum * (1.f / 128.f);
    float c0 = r0 - mean, c1 = r1 - mean, c2 = r2 - mean, c3 = r3 - mean;
    float vs = c0 * c0 + c1 * c1 + c2 * c2 + c3 * c3;
    #pragma unroll
    for (int o = 16; o > 0; o >>= 1) vs += __shfl_xor_sync(0xffffffffu, vs, o);
    float inv = rsqrtf(vs * (1.f / 128.f) + 1e-5f);

    float4 gg = *reinterpret_cast<const float4*>(ln_g + j0);
    float4 bb = *reinterpret_cast<const float4*>(ln_b + j0);
    float4 outv;
    outv.x = c0 * inv * gg.x + bb.x;
    outv.y = c1 * inv * gg.y + bb.y;
    outv.z = c2 * inv * gg.z + bb.z;
    outv.w = c3 * inv * gg.w + bb.w;
    *reinterpret_cast<float4*>(hout + (size_t)n * HIDD + j0) = outv;
}

// ---------------- launch ---------------------------------------------------
static inline void* symp(const void* symbol) {
    void* p = nullptr;
    cudaGetSymbolAddress(&p, symbol);
    return p;
}

extern "C" void kernel_launch(void* const* d_in, const int* in_sizes, int n_in,
                              void* d_out, int out_size)
{
    const float* x     = (const float*)d_in[0];
    const int*   ei    = (const int*)  d_in[1];
    const float* lin_w = (const float*)d_in[2];
    const float* lin_b = (const float*)d_in[3];
    const int L1 = 4, L2 = 14;

    float*  h  = (float*) symp(g_h);
    float*  h2 = (float*) symp(g_h2);
    float*  q  = (float*) symp(g_q);
    __half* kh = (__half*)symp(g_kh);
    __half* vh = (__half*)symp(g_vh);
    float*  s  = (float*) symp(g_s);

    const int smemBytes = SMEM_WORDS * 4;
    cudaFuncSetAttribute(tf32_gemm,
                         cudaFuncAttributeMaxDynamicSharedMemorySize, smemBytes);

    dim3 blk(256);
    dim3 gblk(512);
    const int rowBlocks = (NN + 127) / 128;   // 157

    auto launch_fused = [&](const float* hin, int base) {
        GemmArgs ga = {};
        ga.A = hin;
        ga.B[0] = (const float*)d_in[base + 0]; ga.bias[0] = (const float*)d_in[base + 1];
        ga.C[0] = q;  ga.Ncols[0] = QKVD; ga.units[0] = QKVD / 128; ga.halfout[0] = 0;
        ga.B[1] = (const float*)d_in[base + 2]; ga.bias[1] = (const float*)d_in[base + 3];
        ga.C[1] = kh; ga.Ncols[1] = QKVD; ga.units[1] = QKVD / 128; ga.halfout[1] = 1;
        ga.B[2] = (const float*)d_in[base + 4]; ga.bias[2] = (const float*)d_in[base + 5];
        ga.C[2] = vh; ga.Ncols[2] = QKVD; ga.units[2] = QKVD / 128; ga.halfout[2] = 1;
        ga.B[3] = (const float*)d_in[base + 6]; ga.bias[3] = (const float*)d_in[base + 7];
        ga.C[3] = s;  ga.Ncols[3] = HIDD; ga.units[3] = HIDD / 128; ga.halfout[3] = 0;
        ga.K = HIDD; ga.M = NN; ga.relu = 0;
        dim3 grid(13, rowBlocks);
        tf32_gemm<<<grid, gblk, smemBytes>>>(ga);
    };

    init_kernel<<<(NN + 255) / 256, blk>>>();                 // 0
    count_kernel<<<(EE + 255) / 256, blk>>>(ei);              // 1

    // 2: input projection h = relu(x @ lin_w + lin_b)
    {
        GemmArgs ga = {};
        ga.A = x;
        ga.B[0] = lin_w;  ga.bias[0] = lin_b;  ga.C[0] = h;
        ga.Ncols[0] = HIDD; ga.units[0] = HIDD / 128; ga.halfout[0] = 0;
        ga.K = INDIM; ga.M = NN; ga.relu = 1;
        dim3 grid(ga.units[0], rowBlocks);
        tf32_gemm<<<grid, gblk, smemBytes>>>(ga);
    }

    launch_fused(h, L1);                                      // 3  <-- profiled

    block_sum_kernel<<<NB, blk>>>();                          // 4
    bsum_scan_kernel<<<1, 128>>>();                           // 5
    rowptr_kernel<<<NB, blk>>>();                             // 6
    scatter_kernel<<<(EE + 255) / 256, blk>>>(ei);            // 7

    // 8: attention layer 1
    {
        const float* lg = (const float*)d_in[L1 + 8];
        const float* lb = (const float*)d_in[L1 + 9];
        dim3 gatt((NN + 7) / 8);
        attn_kernel<<<gatt, blk>>>(q, kh, vh, s, h, lg, lb, h2);
    }

    launch_fused(h2, L2);                                     // 9

    // 10: attention layer 2
    {
        const float* lg = (const float*)d_in[L2 + 8];
        const float* lb = (const float*)d_in[L2 + 9];
        dim3 gatt((NN + 7) / 8);
        attn_kernel<<<gatt, blk>>>(q, kh, vh, s, h2, lg, lb, (float*)d_out);
    }
}